// round 13
// baseline (speedup 1.0000x reference)
#include <cuda_runtime.h>
#include <math.h>

#define RMIN 10
#define GAP  40
#define RR   41
#define PP   128
#define NSTEP 32
#define BB   16384
#define MCN  10000
#define DT_F 0.03125f
#define PI_F 3.14159265358979323846f
#define NPAD 3328       // 41*81 = 3321 padded
#define NBLK 52
#define CROW 68         // 64 coeffs + c0 + 3 pad
#define NCHG 8          // g-part chunks: 8*33 = 264 blocks
#define NCHJ 9          // j-part chunks: 9*32 = 288 blocks
#define RGRP 6
#define NN_BLOCKS (NCHG * (NSTEP + 1) + NCHJ * NSTEP)   // 264 + 288 = 552

typedef unsigned long long ull;

// ---------------- f32x2 packed helpers ----------------
__device__ __forceinline__ ull pack2(float lo, float hi) {
    ull r;
    asm("mov.b64 %0, {%1, %2};" : "=l"(r) : "f"(lo), "f"(hi));
    return r;
}
__device__ __forceinline__ ull fma2(ull a, ull b, ull c) {
    ull d;
    asm("fma.rn.f32x2 %0, %1, %2, %3;" : "=l"(d) : "l"(a), "l"(b), "l"(c));
    return d;
}
__device__ __forceinline__ float2 unpk(ull v) {
    float2 f;
    asm("mov.b64 {%0, %1}, %2;" : "=f"(f.x), "=f"(f.y) : "l"(v));
    return f;
}

// ---------------- device scratch ----------------
__device__ float g_jm[RR * 80];
__device__ float g_cr[RR];
__device__ float g_cfr[RR];
__device__ int   g_hist[RR * 80];
__device__ float g_mcjump[RR * PP];
__device__ float g_W3Eu[RR * 64];
__device__ float g_b3Eu[RR];
__device__ float g_W3Eg[NSTEP * RR * 192];
__device__ float g_b3Eg[NSTEP * RR * 3];
__device__ float g_C[(size_t)NSTEP * NPAD * CROW];   // ~29 MB
__device__ float4 g_A[NSTEP * BB];
__device__ float4 g_M[NSTEP * BB];
__device__ float  g_partG[(NSTEP + 1) * BB];
__device__ float  g_partJ[NSTEP * BB];

// upper bound on non-decreasing 80-row: #(row[j] <= u)
__device__ __forceinline__ int ubound80(const float* __restrict__ row, float u) {
    int lo = 0, hi = 80;
    while (lo < hi) {
        int mid = (lo + hi) >> 1;
        if (row[mid] <= u) lo = mid + 1; else hi = mid;
    }
    return lo;
}

// ---------------- tables (+ hist zero) ----------------
__global__ void k_tables() {
    int tid = threadIdx.x;
    for (int i = tid; i < RR * 80; i += 64) g_hist[i] = 0;
    int r = tid;
    if (r >= RR) return;
    float cum = 0.f, slam = 0.f, smu = 0.f;
    for (int k = 1; k <= GAP; k++) {
        float kk = (float)k;
        float lam = ((r + RMIN + k) <= RMIN + GAP) ? 1.0f / (kk * kk) : 0.0f;
        slam += lam; cum += lam;
        g_jm[r * 80 + (k - 1)] = cum;
    }
    for (int k = 1; k <= GAP; k++) {
        float kk = (float)k;
        float mu = ((r + RMIN - k) >= RMIN) ? 1.0f / (kk * kk) : 0.0f;
        smu += mu; cum += mu;
        g_jm[r * 80 + GAP + (k - 1)] = cum;
    }
    g_cr[r] = cum;
    g_cfr[r] = slam + smu - cum;
    for (int j = 0; j < 80; j++) g_jm[r * 80 + j] /= cum;
}

__global__ void k_mc_hist(const float* __restrict__ u_mc) {
    int i = blockIdx.x * blockDim.x + threadIdx.x;
    if (i >= MCN * RR) return;
    int r = i % RR;
    int ind = ubound80(&g_jm[r * 80], u_mc[i]);
    atomicAdd(&g_hist[r * 80 + ind], 1);
}

__global__ void k_mc_combine(const float* __restrict__ jump_l) {
    int idx = blockIdx.x * blockDim.x + threadIdx.x;
    if (idx >= RR * PP) return;
    int r = idx / PP, p = idx % PP;
    float s = 0.f;
    for (int b = 0; b < 80; b++) {
        int c = g_hist[r * 80 + b];
        if (c) s += (float)c * jump_l[b * PP + p];
    }
    g_mcjump[idx] = s * (1.0f / (float)MCN) * g_cr[r];
}

// ---------------- W3E build: one CTA per (r-group of 6, t); t=NSTEP -> u-net ----------------
__global__ void __launch_bounds__(256, 1)
k_build_w3e(const float* __restrict__ guW3, const float* __restrict__ gub3,
            const float* __restrict__ guE,
            const float* __restrict__ uW3, const float* __restrict__ ub3,
            const float* __restrict__ uE) {
    __shared__ float sW[64 * 129];
    __shared__ float sE6[RGRP * 384];
    int rb = blockIdx.x * RGRP, t = blockIdx.y, tid = threadIdx.x;
    int nr = (RR - rb < RGRP) ? (RR - rb) : RGRP;
    if (t < NSTEP) {
        for (int idx = tid; idx < 8192; idx += 256) {
            int j = idx >> 7, p = idx & 127;
            sW[j * 129 + p] = guW3[(size_t)t * 8192 + idx];
        }
        for (int idx = tid; idx < nr * 384; idx += 256)
            sE6[idx] = guE[((size_t)t * RR + rb) * 384 + idx];
        __syncthreads();
        for (int idx = tid; idx < nr * 192; idx += 256) {
            int rr = idx / 192, c = idx - rr * 192;
            int j = c & 63, o = c >> 6;
            const float* w = sW + j * 129;
            const float* e = sE6 + rr * 384 + o;
            float acc = 0.f;
#pragma unroll 8
            for (int p = 0; p < 128; p++) acc = fmaf(w[p], e[p * 3], acc);
            g_W3Eg[((size_t)t * RR + rb + rr) * 192 + j * 3 + o] = acc;
        }
        if (tid < nr * 3) {
            int rr = tid / 3, o = tid - rr * 3;
            const float* b = gub3 + t * 128;
            const float* e = sE6 + rr * 384 + o;
            float a = 0.f;
#pragma unroll 8
            for (int p = 0; p < 128; p++) a = fmaf(b[p], e[p * 3], a);
            g_b3Eg[(t * RR + rb + rr) * 3 + o] = a;
        }
    } else {
        for (int idx = tid; idx < 8192; idx += 256) {
            int j = idx >> 7, p = idx & 127;
            sW[j * 129 + p] = uW3[idx];
        }
        for (int idx = tid; idx < nr * 128; idx += 256) sE6[idx] = uE[rb * 128 + idx];
        __syncthreads();
        for (int idx = tid; idx < nr * 64; idx += 256) {
            int rr = idx >> 6, j = idx & 63;
            const float* w = sW + j * 129;
            const float* e = sE6 + rr * 128;
            float acc = 0.f;
#pragma unroll 8
            for (int p = 0; p < 128; p++) acc = fmaf(w[p], e[p], acc);
            g_W3Eu[(rb + rr) * 64 + j] = acc;
        }
        if (tid < nr) {
            const float* e = sE6 + tid * 128;
            float acc = 0.f;
#pragma unroll 8
            for (int p = 0; p < 128; p++) acc = fmaf(ub3[p], e[p], acc);
            g_b3Eu[rb + tid] = acc;
        }
    }
}

// ---------------- C table build: FFMA2 + coalesced float4 stores ----------------
#define CPAD 68
#define SMEM_C_FLOATS (2 * 128 * CPAD)
__global__ void __launch_bounds__(256, 1)
k_build_C(const float* __restrict__ jxW3, const float* __restrict__ jxb3,
          const float* __restrict__ jump_r, const float* __restrict__ jump_l) {
    extern __shared__ float smc[];
    float* smA = smc;                 // [128][68]: smA[p][j]
    float* smB = smc + 128 * CPAD;    // [128][68]: smB[p][n]
    int nblk = blockIdx.x, t = blockIdx.y, tid = threadIdx.x;

    for (int idx = tid; idx < 8192; idx += 256) {
        int j = idx >> 7, p = idx & 127;
        smA[p * CPAD + j] = jxW3[(size_t)t * 8192 + idx];
    }
    for (int idx = tid; idx < 8192; idx += 256) {
        int n = idx >> 7, p = idx & 127;
        int n_g = nblk * 64 + n;
        float b = 0.f;
        if (n_g < RR * 81) {
            int r = n_g / 81, d = n_g - r * 81;
            float jl = 0.f;
            if (d > 40)      jl = jump_l[(d - 41) * PP + p];
            else if (d < 40) jl = jump_l[(79 - d) * PP + p];
            b = jump_r[r * PP + p] * (jl - g_mcjump[r * PP + p] * DT_F);
        }
        smB[p * CPAD + n] = b;
    }
    __syncthreads();

    int tx = tid & 15, ty = tid >> 4;
    ull acc[4][2];
#pragma unroll
    for (int n = 0; n < 4; n++) { acc[n][0] = 0ull; acc[n][1] = 0ull; }
#pragma unroll 4
    for (int p = 0; p < 128; p++) {
        longlong2 aj = *(const longlong2*)(smA + p * CPAD + tx * 4);
        float4 bn = *(const float4*)(smB + p * CPAD + ty * 4);
        ull b0 = pack2(bn.x, bn.x), b1 = pack2(bn.y, bn.y);
        ull b2 = pack2(bn.z, bn.z), b3 = pack2(bn.w, bn.w);
        acc[0][0] = fma2(b0, (ull)aj.x, acc[0][0]);
        acc[0][1] = fma2(b0, (ull)aj.y, acc[0][1]);
        acc[1][0] = fma2(b1, (ull)aj.x, acc[1][0]);
        acc[1][1] = fma2(b1, (ull)aj.y, acc[1][1]);
        acc[2][0] = fma2(b2, (ull)aj.x, acc[2][0]);
        acc[2][1] = fma2(b2, (ull)aj.y, acc[2][1]);
        acc[3][0] = fma2(b3, (ull)aj.x, acc[3][0]);
        acc[3][1] = fma2(b3, (ull)aj.y, acc[3][1]);
    }
#pragma unroll
    for (int n = 0; n < 4; n++) {
        int n_g = nblk * 64 + ty * 4 + n;
        float2 lo = unpk(acc[n][0]);
        float2 hi = unpk(acc[n][1]);
        float4 v; v.x = lo.x; v.y = lo.y; v.z = hi.x; v.w = hi.y;
        *(float4*)(g_C + ((size_t)t * NPAD + n_g) * CROW + tx * 4) = v;
    }
    if (tid < 64) {
        int n_g = nblk * 64 + tid;
        const float* b3 = jxb3 + t * 128;
        float c0 = 0.f;
#pragma unroll 4
        for (int p = 0; p < 128; p++) c0 = fmaf(b3[p], smB[p * CPAD + tid], c0);
        size_t base = ((size_t)t * NPAD + n_g) * CROW;
        g_C[base + 64] = c0;
        g_C[base + 65] = 0.f; g_C[base + 66] = 0.f; g_C[base + 67] = 0.f;
    }
}

// ---------------- geometry pass: trajectory only, NN-free ----------------
__global__ void __launch_bounds__(128)
k_geom(const int* __restrict__ rt0, const float* __restrict__ xt0,
       const float* __restrict__ dBt, const float* __restrict__ u_jump,
       const float* __restrict__ u_size, float* __restrict__ out) {
    __shared__ float sJM[RR * 80];
    __shared__ float sCR[RR];
    __shared__ float sCF[RR];
    int tid = threadIdx.x;
    for (int idx = tid; idx < RR * 80; idx += 128) sJM[idx] = g_jm[idx];
    for (int idx = tid; idx < RR; idx += 128) {
        sCR[idx] = g_cr[idx];
        sCF[idx] = g_cfr[idx];
    }
    __syncthreads();

    int i = blockIdx.x * 128 + tid;
    const float sqDT = 0.17677669529663688985f;   // sqrt(1/32)
    const float sq2D = 1.41421356237309504880f;   // sqrt(2)
    int rt = rt0[i];
    float x0 = xt0[i * 3 + 0], x1 = xt0[i * 3 + 1], x2 = xt0[i * 3 + 2];
    float xi0 = x0, xi1 = x1, xi2 = x2;
    float sgn = 1.f, fun = 0.f;

#pragma unroll 1
    for (int t = 0; t < NSTEP; t++) {
        int ridx = rt - RMIN;
        float uj = u_jump[t * BB + i];
        int drt = 0;
        if (uj < sCR[ridx] * DT_F) {
            int ind = ubound80(sJM + ridx * 80, u_size[t * BB + i]);
            drt = (ind < GAP) ? (ind + 1) : -(ind - GAP + 1);
        }

        float rn = sqrtf(x0 * x0 + x1 * x1 + x2 * x2);
        float cz = fminf(fmaxf(x2 / rn, -1.0f), 1.0f);
        float theta = acosf(cz) - 0.5f * PI_F;
        float phi = atan2f(x1, x0);
        float st, ct, sp, cpv;
        __sincosf(theta, &st, &ct);
        __sincosf(phi, &sp, &cpv);
        float T00 = cpv * ct, T01 = -sp,  T02 = cpv * st;
        float T10 = sp * ct,  T11 = cpv,  T12 = sp * st;
        float T20 = -st,      T22 = ct;

        float2 db = ((const float2*)dBt)[t * BB + i];
        float dB0 = db.x * sqDT, dB1 = db.y * sqDT;
        float rtf = (float)rt;
        float c1 = sq2D / rtf;
        float ef = __expf(-fun);

        float m0 = ef * c1 * (T01 * dB1 - T02 * dB0);
        float m1 = ef * c1 * (T11 * dB1 - T12 * dB0);
        float m2 = -ef * c1 * sgn * T22 * dB0;
        float4 av; av.x = xi0; av.y = xi1; av.z = xi2; av.w = ef;
        g_A[t * BB + i] = av;
        float4 mv; mv.x = m0; mv.y = m1; mv.z = m2;
        mv.w = __int_as_float(ridx | ((drt + 40) << 8));
        g_M[t * BB + i] = mv;

        fun += sCF[ridx] * DT_F;

        float dX20 = c1 * dB0, dX21 = c1 * dB1;
        float th_d = dX20 + 0.5f * PI_F;
        float sth, cth, sph, cph;
        __sincosf(th_d, &sth, &cth);
        __sincosf(dX21, &sph, &cph);
        float d30 = sth * cph - 1.0f;
        float d31 = sth * sph;
        float d32 = cth;
        float dX0 = T00 * d30 + T01 * d31 + T02 * d32;
        float dX1 = T10 * d30 + T11 * d31 + T12 * d32;
        float dX2 = T20 * d30 + T22 * d32;     // T21 = 0
        x0 += dX0; x1 += dX1; x2 += dX2;
        xi0 += dX0; xi1 += dX1; xi2 += sgn * dX2;
        rt += drt;
        if (xi2 < 0.f) { xi2 = -xi2; sgn = -sgn; }
    }

    float ef = __expf(-fun);
    out[BB + i] = (xi0 * xi0 + xi1 * xi1 + xi2 * xi2) / (float)rt * ef;
}

// ---------------- helpers ----------------
__device__ __forceinline__ void cp4s(float* dst, const float* __restrict__ src,
                                     int nfl, int tid) {
    const float4* s = (const float4*)src;
    float4* d = (float4*)dst;
    int n4 = nfl >> 2;
    for (int i = tid; i < n4; i += 256) d[i] = s[i];
}

// tanh = 1 - 2/(1+e^{2x}); clamp-free
__device__ __forceinline__ float tanh_fast(float x) {
    float e = __expf(2.0f * x);
    float r = __fdividef(1.0f, e + 1.0f);
    return fmaf(-2.0f, r, 1.0f);
}

// layer1: x(3) -> tanh(64); weights W1 @0 [3][64], b1 @192
__device__ __forceinline__ void layer1(const float* __restrict__ W,
                                       float x0, float x1, float x2, float* h1) {
#pragma unroll
    for (int j = 0; j < 64; j += 4) {
        float4 wa = *(const float4*)(W + j);
        float4 wb = *(const float4*)(W + 64 + j);
        float4 wc = *(const float4*)(W + 128 + j);
        float4 bb = *(const float4*)(W + 192 + j);
        h1[j + 0] = tanh_fast(fmaf(x0, wa.x, fmaf(x1, wb.x, fmaf(x2, wc.x, bb.x))));
        h1[j + 1] = tanh_fast(fmaf(x0, wa.y, fmaf(x1, wb.y, fmaf(x2, wc.y, bb.y))));
        h1[j + 2] = tanh_fast(fmaf(x0, wa.z, fmaf(x1, wb.z, fmaf(x2, wc.z, bb.z))));
        h1[j + 3] = tanh_fast(fmaf(x0, wa.w, fmaf(x1, wb.w, fmaf(x2, wc.w, bb.w))));
    }
}

// layer2 16-output pass via packed FFMA2
__device__ __forceinline__ void layer2_pass16(const float* __restrict__ W2,
                                              const float* __restrict__ b2,
                                              const float* __restrict__ h1,
                                              int cbase, float* y) {
    ull A[8];
    {
        const longlong2* bb = (const longlong2*)(b2 + cbase);
#pragma unroll
        for (int q = 0; q < 4; q++) {
            longlong2 v = bb[q];
            A[2 * q] = (ull)v.x; A[2 * q + 1] = (ull)v.y;
        }
    }
#pragma unroll
    for (int j = 0; j < 64; j++) {
        ull hp = pack2(h1[j], h1[j]);
        const longlong2* w = (const longlong2*)(W2 + j * 64 + cbase);
#pragma unroll
        for (int q = 0; q < 4; q++) {
            longlong2 wv = w[q];
            A[2 * q]     = fma2(hp, (ull)wv.x, A[2 * q]);
            A[2 * q + 1] = fma2(hp, (ull)wv.y, A[2 * q + 1]);
        }
    }
#pragma unroll
    for (int q = 0; q < 8; q++) {
        float2 f = unpk(A[q]);
        y[2 * q]     = tanh_fast(f.x);
        y[2 * q + 1] = tanh_fast(f.y);
    }
}

// ---------------- fused NN kernel: g-part (264 blocks) | j-part (288 blocks) ----------------
// g smem: gW 4416 | E 7872 | B3E 128 = 12416 floats (48.5 KB); j uses first 4416
#define SG_W    0
#define SG_E    4416
#define SG_B3E  12288
#define SG_TOT  12416
__global__ void __launch_bounds__(256, 2)
k_mega_nn(const float* __restrict__ xt0, const int* __restrict__ rt0,
          const float* __restrict__ uW1, const float* __restrict__ ub1,
          const float* __restrict__ uW2, const float* __restrict__ ub2,
          const float* __restrict__ guW1, const float* __restrict__ gub1,
          const float* __restrict__ guW2, const float* __restrict__ gub2,
          const float* __restrict__ jxW1, const float* __restrict__ jxb1,
          const float* __restrict__ jxW2, const float* __restrict__ jxb2) {
    extern __shared__ float sm[];
    int bid = blockIdx.x, tid = threadIdx.x;

    float h1[64];
    float y[16];

    if (bid < NCHG * (NSTEP + 1)) {
        // ---------------- g-net / u0 ----------------
        int chunk = bid % NCHG, t = bid / NCHG;
        if (t < NSTEP) {
            cp4s(sm + SG_W,        guW1 + t * 192,  192,  tid);
            cp4s(sm + SG_W + 192,  gub1 + t * 64,   64,   tid);
            cp4s(sm + SG_W + 256,  guW2 + t * 4096, 4096, tid);
            cp4s(sm + SG_W + 4352, gub2 + t * 64,   64,   tid);
            const float* wsrc = g_W3Eg + (size_t)t * RR * 192;
            for (int idx = tid; idx < RR * 192; idx += 256) {
                int r = idx / 192, c = idx - r * 192;
                sm[SG_E + c * 41 + r] = wsrc[idx];
            }
            const float* bsrc = g_b3Eg + t * RR * 3;
            for (int idx = tid; idx < RR * 3; idx += 256) {
                int r = idx / 3, o = idx - r * 3;
                sm[SG_B3E + o * 41 + r] = bsrc[idx];
            }
        } else {
            cp4s(sm + SG_W, uW1, 192, tid);
            cp4s(sm + SG_W + 192, ub1, 64, tid);
            cp4s(sm + SG_W + 256, uW2, 4096, tid);
            cp4s(sm + SG_W + 4352, ub2, 64, tid);
            for (int idx = tid; idx < RR * 64; idx += 256) {
                int r = idx >> 6, j = idx & 63;
                sm[SG_E + j * 41 + r] = g_W3Eu[idx];
            }
            for (int idx = tid; idx < RR; idx += 256) sm[SG_B3E + idx] = g_b3Eu[idx];
        }
        __syncthreads();

        if (t < NSTEP) {
#pragma unroll 1
            for (int k = 0; k < 8; k++) {
                int i = chunk * 256 + k * (NCHG * 256) + tid;
                if (i >= BB) break;
                float4 av = g_A[t * BB + i];
                float4 mv = g_M[t * BB + i];
                int ridx = __float_as_int(mv.w) & 0xFF;

                layer1(sm + SG_W, av.x, av.y, av.z, h1);
                float gu0 = sm[SG_B3E + ridx];
                float gu1 = sm[SG_B3E + 41 + ridx];
                float gu2 = sm[SG_B3E + 82 + ridx];
#pragma unroll 1
                for (int pass = 0; pass < 4; pass++) {
                    layer2_pass16(sm + SG_W + 256, sm + SG_W + 4352, h1, pass * 16, y);
#pragma unroll
                    for (int q = 0; q < 16; q++) {
                        const float* e = sm + SG_E + ((pass * 16 + q) * 3) * 41 + ridx;
                        gu0 = fmaf(y[q], e[0], gu0);
                        gu1 = fmaf(y[q], e[41], gu1);
                        gu2 = fmaf(y[q], e[82], gu2);
                    }
                }
                g_partG[t * BB + i] = gu0 * mv.x + gu1 * mv.y + gu2 * mv.z;
            }
        } else {
#pragma unroll 1
            for (int k = 0; k < 8; k++) {
                int i = chunk * 256 + k * (NCHG * 256) + tid;
                if (i >= BB) break;
                float x0 = xt0[i * 3 + 0], x1 = xt0[i * 3 + 1], x2 = xt0[i * 3 + 2];
                int ridx = rt0[i] - RMIN;
                layer1(sm + SG_W, x0, x1, x2, h1);
                float u = sm[SG_B3E + ridx];
#pragma unroll 1
                for (int pass = 0; pass < 4; pass++) {
                    layer2_pass16(sm + SG_W + 256, sm + SG_W + 4352, h1, pass * 16, y);
#pragma unroll
                    for (int q = 0; q < 16; q++)
                        u = fmaf(y[q], sm[SG_E + (pass * 16 + q) * 41 + ridx], u);
                }
                g_partG[NSTEP * BB + i] = u;
            }
        }
    } else {
        // ---------------- j-net ----------------
        int id = bid - NCHG * (NSTEP + 1);
        int chunk = id % NCHJ, t = id / NCHJ;

        cp4s(sm,        jxW1 + t * 192,  192,  tid);
        cp4s(sm + 192,  jxb1 + t * 64,   64,   tid);
        cp4s(sm + 256,  jxW2 + t * 4096, 4096, tid);
        cp4s(sm + 4352, jxb2 + t * 64,   64,   tid);
        __syncthreads();

#pragma unroll 1
        for (int k = 0; k < 8; k++) {
            int i = chunk * 256 + k * (NCHJ * 256) + tid;
            if (i >= BB) break;
            float4 av = g_A[t * BB + i];
            float4 mv = g_M[t * BB + i];
            int bits = __float_as_int(mv.w);
            int ridx = bits & 0xFF;
            int n = ridx * 81 + (bits >> 8);
            const float* crow = g_C + ((size_t)t * NPAD + n) * CROW;
            asm volatile("prefetch.global.L1 [%0];" :: "l"(crow));
            asm volatile("prefetch.global.L1 [%0];" :: "l"(crow + 32));
            asm volatile("prefetch.global.L1 [%0];" :: "l"(crow + 64));

            layer1(sm, av.x, av.y, av.z, h1);
            float jmp = crow[64];   // c0
            const float4* crow4 = (const float4*)crow;
#pragma unroll 1
            for (int pass = 0; pass < 4; pass++) {
                layer2_pass16(sm + 256, sm + 4352, h1, pass * 16, y);
                float4 c0 = crow4[pass * 4 + 0];
                float4 c1 = crow4[pass * 4 + 1];
                float4 c2 = crow4[pass * 4 + 2];
                float4 c3 = crow4[pass * 4 + 3];
                jmp = fmaf(y[0],  c0.x, jmp); jmp = fmaf(y[1],  c0.y, jmp);
                jmp = fmaf(y[2],  c0.z, jmp); jmp = fmaf(y[3],  c0.w, jmp);
                jmp = fmaf(y[4],  c1.x, jmp); jmp = fmaf(y[5],  c1.y, jmp);
                jmp = fmaf(y[6],  c1.z, jmp); jmp = fmaf(y[7],  c1.w, jmp);
                jmp = fmaf(y[8],  c2.x, jmp); jmp = fmaf(y[9],  c2.y, jmp);
                jmp = fmaf(y[10], c2.z, jmp); jmp = fmaf(y[11], c2.w, jmp);
                jmp = fmaf(y[12], c3.x, jmp); jmp = fmaf(y[13], c3.y, jmp);
                jmp = fmaf(y[14], c3.z, jmp); jmp = fmaf(y[15], c3.w, jmp);
            }
            g_partJ[t * BB + i] = av.w * jmp;
        }
    }
}

// ---------------- reduction ----------------
__global__ void __launch_bounds__(256)
k_reduce(float* __restrict__ out) {
    int i = blockIdx.x * 256 + threadIdx.x;
    float s = g_partG[NSTEP * BB + i];
#pragma unroll 1
    for (int t = 0; t < NSTEP; t++) s += g_partG[t * BB + i] + g_partJ[t * BB + i];
    out[i] = s;
}

// ---------------- launcher ----------------
extern "C" void kernel_launch(void* const* d_in, const int* in_sizes, int n_in,
                              void* d_out, int out_size) {
    const int*   rt0    = (const int*)d_in[1];
    const float* xt0    = (const float*)d_in[2];
    const float* dBt    = (const float*)d_in[3];
    const float* u_jump = (const float*)d_in[4];
    const float* u_size = (const float*)d_in[5];
    const float* u_mc   = (const float*)d_in[6];
    const float* uW1 = (const float*)d_in[7];
    const float* ub1 = (const float*)d_in[8];
    const float* uW2 = (const float*)d_in[9];
    const float* ub2 = (const float*)d_in[10];
    const float* uW3 = (const float*)d_in[11];
    const float* ub3 = (const float*)d_in[12];
    const float* uE  = (const float*)d_in[13];
    const float* guW1 = (const float*)d_in[14];
    const float* gub1 = (const float*)d_in[15];
    const float* guW2 = (const float*)d_in[16];
    const float* gub2 = (const float*)d_in[17];
    const float* guW3 = (const float*)d_in[18];
    const float* gub3 = (const float*)d_in[19];
    const float* guE  = (const float*)d_in[20];
    const float* jxW1 = (const float*)d_in[21];
    const float* jxb1 = (const float*)d_in[22];
    const float* jxW2 = (const float*)d_in[23];
    const float* jxb2 = (const float*)d_in[24];
    const float* jxW3 = (const float*)d_in[25];
    const float* jxb3 = (const float*)d_in[26];
    const float* jump_r = (const float*)d_in[27];
    const float* jump_l = (const float*)d_in[28];
    float* out = (float*)d_out;

    cudaFuncSetAttribute(k_build_C, cudaFuncAttributeMaxDynamicSharedMemorySize,
                         SMEM_C_FLOATS * 4);
    cudaFuncSetAttribute(k_mega_nn, cudaFuncAttributeMaxDynamicSharedMemorySize,
                         SG_TOT * 4);

    k_tables<<<1, 64>>>();
    k_mc_hist<<<(MCN * RR + 255) / 256, 256>>>(u_mc);
    k_mc_combine<<<(RR * PP + 127) / 128, 128>>>(jump_l);
    k_build_w3e<<<dim3((RR + RGRP - 1) / RGRP, NSTEP + 1), 256>>>(
        guW3, gub3, guE, uW3, ub3, uE);
    k_build_C<<<dim3(NBLK, NSTEP), 256, SMEM_C_FLOATS * 4>>>(jxW3, jxb3, jump_r, jump_l);
    k_geom<<<BB / 128, 128>>>(rt0, xt0, dBt, u_jump, u_size, out);
    k_mega_nn<<<NN_BLOCKS, 256, SG_TOT * 4>>>(
        xt0, rt0, uW1, ub1, uW2, ub2,
        guW1, gub1, guW2, gub2,
        jxW1, jxb1, jxW2, jxb2);
    k_reduce<<<BB / 256, 256>>>(out);
    (void)in_sizes; (void)n_in; (void)out_size;
}

// round 14
// speedup vs baseline: 1.1598x; 1.1598x over previous
#include <cuda_runtime.h>
#include <math.h>

#define RMIN 10
#define GAP  40
#define RR   41
#define PP   128
#define NSTEP 32
#define BB   16384
#define MCN  10000
#define DT_F 0.03125f
#define PI_F 3.14159265358979323846f
#define NPAD 3328       // 41*81 = 3321 padded
#define NBLK 52
#define CROW 68         // 64 coeffs + c0 + 3 pad
#define NCH  9          // k_nn sample chunks (9*33 = 297 blocks ~ 1 wave)
#define RGRP 6

typedef unsigned long long ull;

// ---------------- f32x2 packed helpers ----------------
__device__ __forceinline__ ull pack2(float lo, float hi) {
    ull r;
    asm("mov.b64 %0, {%1, %2};" : "=l"(r) : "f"(lo), "f"(hi));
    return r;
}
__device__ __forceinline__ ull fma2(ull a, ull b, ull c) {
    ull d;
    asm("fma.rn.f32x2 %0, %1, %2, %3;" : "=l"(d) : "l"(a), "l"(b), "l"(c));
    return d;
}
__device__ __forceinline__ float2 unpk(ull v) {
    float2 f;
    asm("mov.b64 {%0, %1}, %2;" : "=f"(f.x), "=f"(f.y) : "l"(v));
    return f;
}

// ---------------- device scratch ----------------
__device__ float g_jm[RR * 80];
__device__ float g_cr[RR];
__device__ float g_cfr[RR];
__device__ int   g_hist[RR * 80];
__device__ float g_mcjump[RR * PP];
__device__ float g_W3Eu[RR * 64];
__device__ float g_b3Eu[RR];
__device__ float g_W3Eg[NSTEP * RR * 192];
__device__ float g_b3Eg[NSTEP * RR * 3];
__device__ float g_C[(size_t)NSTEP * NPAD * CROW];   // ~29 MB
__device__ float4 g_A[NSTEP * BB];                   // xi0,xi1,xi2, ef
__device__ float4 g_M[NSTEP * BB];                   // m0,m1,m2, bits(ridx|d<<8)
__device__ float  g_part[(NSTEP + 1) * BB];

// upper bound on non-decreasing 80-row: #(row[j] <= u)
__device__ __forceinline__ int ubound80(const float* __restrict__ row, float u) {
    int lo = 0, hi = 80;
    while (lo < hi) {
        int mid = (lo + hi) >> 1;
        if (row[mid] <= u) lo = mid + 1; else hi = mid;
    }
    return lo;
}

// ---------------- tables (+ hist zero) ----------------
__global__ void k_tables() {
    int tid = threadIdx.x;
    for (int i = tid; i < RR * 80; i += 64) g_hist[i] = 0;
    int r = tid;
    if (r >= RR) return;
    float cum = 0.f, slam = 0.f, smu = 0.f;
    for (int k = 1; k <= GAP; k++) {
        float kk = (float)k;
        float lam = ((r + RMIN + k) <= RMIN + GAP) ? 1.0f / (kk * kk) : 0.0f;
        slam += lam; cum += lam;
        g_jm[r * 80 + (k - 1)] = cum;
    }
    for (int k = 1; k <= GAP; k++) {
        float kk = (float)k;
        float mu = ((r + RMIN - k) >= RMIN) ? 1.0f / (kk * kk) : 0.0f;
        smu += mu; cum += mu;
        g_jm[r * 80 + GAP + (k - 1)] = cum;
    }
    g_cr[r] = cum;
    g_cfr[r] = slam + smu - cum;
    for (int j = 0; j < 80; j++) g_jm[r * 80 + j] /= cum;
}

__global__ void k_mc_hist(const float* __restrict__ u_mc) {
    int i = blockIdx.x * blockDim.x + threadIdx.x;
    if (i >= MCN * RR) return;
    int r = i % RR;
    int ind = ubound80(&g_jm[r * 80], u_mc[i]);
    atomicAdd(&g_hist[r * 80 + ind], 1);
}

__global__ void k_mc_combine(const float* __restrict__ jump_l) {
    int idx = blockIdx.x * blockDim.x + threadIdx.x;
    if (idx >= RR * PP) return;
    int r = idx / PP, p = idx % PP;
    float s = 0.f;
    for (int b = 0; b < 80; b++) {
        int c = g_hist[r * 80 + b];
        if (c) s += (float)c * jump_l[b * PP + p];
    }
    g_mcjump[idx] = s * (1.0f / (float)MCN) * g_cr[r];
}

// ---------------- W3E build: one CTA per (r-group of 6, t); t=NSTEP -> u-net ----------------
__global__ void __launch_bounds__(256, 1)
k_build_w3e(const float* __restrict__ guW3, const float* __restrict__ gub3,
            const float* __restrict__ guE,
            const float* __restrict__ uW3, const float* __restrict__ ub3,
            const float* __restrict__ uE) {
    __shared__ float sW[64 * 129];
    __shared__ float sE6[RGRP * 384];
    int rb = blockIdx.x * RGRP, t = blockIdx.y, tid = threadIdx.x;
    int nr = (RR - rb < RGRP) ? (RR - rb) : RGRP;
    if (t < NSTEP) {
        for (int idx = tid; idx < 8192; idx += 256) {
            int j = idx >> 7, p = idx & 127;
            sW[j * 129 + p] = guW3[(size_t)t * 8192 + idx];
        }
        for (int idx = tid; idx < nr * 384; idx += 256)
            sE6[idx] = guE[((size_t)t * RR + rb) * 384 + idx];
        __syncthreads();
        for (int idx = tid; idx < nr * 192; idx += 256) {
            int rr = idx / 192, c = idx - rr * 192;
            int j = c & 63, o = c >> 6;
            const float* w = sW + j * 129;
            const float* e = sE6 + rr * 384 + o;
            float acc = 0.f;
#pragma unroll 8
            for (int p = 0; p < 128; p++) acc = fmaf(w[p], e[p * 3], acc);
            g_W3Eg[((size_t)t * RR + rb + rr) * 192 + j * 3 + o] = acc;
        }
        if (tid < nr * 3) {
            int rr = tid / 3, o = tid - rr * 3;
            const float* b = gub3 + t * 128;
            const float* e = sE6 + rr * 384 + o;
            float a = 0.f;
#pragma unroll 8
            for (int p = 0; p < 128; p++) a = fmaf(b[p], e[p * 3], a);
            g_b3Eg[(t * RR + rb + rr) * 3 + o] = a;
        }
    } else {
        for (int idx = tid; idx < 8192; idx += 256) {
            int j = idx >> 7, p = idx & 127;
            sW[j * 129 + p] = uW3[idx];
        }
        for (int idx = tid; idx < nr * 128; idx += 256) sE6[idx] = uE[rb * 128 + idx];
        __syncthreads();
        for (int idx = tid; idx < nr * 64; idx += 256) {
            int rr = idx >> 6, j = idx & 63;
            const float* w = sW + j * 129;
            const float* e = sE6 + rr * 128;
            float acc = 0.f;
#pragma unroll 8
            for (int p = 0; p < 128; p++) acc = fmaf(w[p], e[p], acc);
            g_W3Eu[(rb + rr) * 64 + j] = acc;
        }
        if (tid < nr) {
            const float* e = sE6 + tid * 128;
            float acc = 0.f;
#pragma unroll 8
            for (int p = 0; p < 128; p++) acc = fmaf(ub3[p], e[p], acc);
            g_b3Eu[rb + tid] = acc;
        }
    }
}

// ---------------- C table build: FFMA2 + coalesced float4 stores ----------------
#define CPAD 68
#define SMEM_C_FLOATS (2 * 128 * CPAD)
__global__ void __launch_bounds__(256, 1)
k_build_C(const float* __restrict__ jxW3, const float* __restrict__ jxb3,
          const float* __restrict__ jump_r, const float* __restrict__ jump_l) {
    extern __shared__ float smc[];
    float* smA = smc;                 // [128][68]: smA[p][j]
    float* smB = smc + 128 * CPAD;    // [128][68]: smB[p][n]
    int nblk = blockIdx.x, t = blockIdx.y, tid = threadIdx.x;

    for (int idx = tid; idx < 8192; idx += 256) {
        int j = idx >> 7, p = idx & 127;
        smA[p * CPAD + j] = jxW3[(size_t)t * 8192 + idx];
    }
    for (int idx = tid; idx < 8192; idx += 256) {
        int n = idx >> 7, p = idx & 127;
        int n_g = nblk * 64 + n;
        float b = 0.f;
        if (n_g < RR * 81) {
            int r = n_g / 81, d = n_g - r * 81;
            float jl = 0.f;
            if (d > 40)      jl = jump_l[(d - 41) * PP + p];
            else if (d < 40) jl = jump_l[(79 - d) * PP + p];
            b = jump_r[r * PP + p] * (jl - g_mcjump[r * PP + p] * DT_F);
        }
        smB[p * CPAD + n] = b;
    }
    __syncthreads();

    int tx = tid & 15, ty = tid >> 4;
    ull acc[4][2];
#pragma unroll
    for (int n = 0; n < 4; n++) { acc[n][0] = 0ull; acc[n][1] = 0ull; }
#pragma unroll 4
    for (int p = 0; p < 128; p++) {
        longlong2 aj = *(const longlong2*)(smA + p * CPAD + tx * 4);
        float4 bn = *(const float4*)(smB + p * CPAD + ty * 4);
        ull b0 = pack2(bn.x, bn.x), b1 = pack2(bn.y, bn.y);
        ull b2 = pack2(bn.z, bn.z), b3 = pack2(bn.w, bn.w);
        acc[0][0] = fma2(b0, (ull)aj.x, acc[0][0]);
        acc[0][1] = fma2(b0, (ull)aj.y, acc[0][1]);
        acc[1][0] = fma2(b1, (ull)aj.x, acc[1][0]);
        acc[1][1] = fma2(b1, (ull)aj.y, acc[1][1]);
        acc[2][0] = fma2(b2, (ull)aj.x, acc[2][0]);
        acc[2][1] = fma2(b2, (ull)aj.y, acc[2][1]);
        acc[3][0] = fma2(b3, (ull)aj.x, acc[3][0]);
        acc[3][1] = fma2(b3, (ull)aj.y, acc[3][1]);
    }
#pragma unroll
    for (int n = 0; n < 4; n++) {
        int n_g = nblk * 64 + ty * 4 + n;
        float2 lo = unpk(acc[n][0]);
        float2 hi = unpk(acc[n][1]);
        float4 v; v.x = lo.x; v.y = lo.y; v.z = hi.x; v.w = hi.y;
        *(float4*)(g_C + ((size_t)t * NPAD + n_g) * CROW + tx * 4) = v;
    }
    if (tid < 64) {
        int n_g = nblk * 64 + tid;
        const float* b3 = jxb3 + t * 128;
        float c0 = 0.f;
#pragma unroll 4
        for (int p = 0; p < 128; p++) c0 = fmaf(b3[p], smB[p * CPAD + tid], c0);
        size_t base = ((size_t)t * NPAD + n_g) * CROW;
        g_C[base + 64] = c0;
        g_C[base + 65] = 0.f; g_C[base + 66] = 0.f; g_C[base + 67] = 0.f;
    }
}

// ---------------- geometry pass: trajectory only, NN-free ----------------
__global__ void __launch_bounds__(128)
k_geom(const int* __restrict__ rt0, const float* __restrict__ xt0,
       const float* __restrict__ dBt, const float* __restrict__ u_jump,
       const float* __restrict__ u_size, float* __restrict__ out) {
    __shared__ float sJM[RR * 80];
    __shared__ float sCR[RR];
    __shared__ float sCF[RR];
    int tid = threadIdx.x;
    for (int idx = tid; idx < RR * 80; idx += 128) sJM[idx] = g_jm[idx];
    for (int idx = tid; idx < RR; idx += 128) {
        sCR[idx] = g_cr[idx];
        sCF[idx] = g_cfr[idx];
    }
    __syncthreads();

    int i = blockIdx.x * 128 + tid;
    const float sqDT = 0.17677669529663688985f;   // sqrt(1/32)
    const float sq2D = 1.41421356237309504880f;   // sqrt(2)
    int rt = rt0[i];
    float x0 = xt0[i * 3 + 0], x1 = xt0[i * 3 + 1], x2 = xt0[i * 3 + 2];
    float xi0 = x0, xi1 = x1, xi2 = x2;
    float sgn = 1.f, fun = 0.f;

#pragma unroll 1
    for (int t = 0; t < NSTEP; t++) {
        int ridx = rt - RMIN;
        float uj = u_jump[t * BB + i];
        int drt = 0;
        if (uj < sCR[ridx] * DT_F) {
            int ind = ubound80(sJM + ridx * 80, u_size[t * BB + i]);
            drt = (ind < GAP) ? (ind + 1) : -(ind - GAP + 1);
        }

        float rn = sqrtf(x0 * x0 + x1 * x1 + x2 * x2);
        float cz = fminf(fmaxf(x2 / rn, -1.0f), 1.0f);
        float theta = acosf(cz) - 0.5f * PI_F;
        float phi = atan2f(x1, x0);
        float st, ct, sp, cpv;
        __sincosf(theta, &st, &ct);
        __sincosf(phi, &sp, &cpv);
        float T00 = cpv * ct, T01 = -sp,  T02 = cpv * st;
        float T10 = sp * ct,  T11 = cpv,  T12 = sp * st;
        float T20 = -st,      T22 = ct;

        float2 db = ((const float2*)dBt)[t * BB + i];
        float dB0 = db.x * sqDT, dB1 = db.y * sqDT;
        float rtf = (float)rt;
        float c1 = sq2D / rtf;
        float ef = __expf(-fun);

        float m0 = ef * c1 * (T01 * dB1 - T02 * dB0);
        float m1 = ef * c1 * (T11 * dB1 - T12 * dB0);
        float m2 = -ef * c1 * sgn * T22 * dB0;
        float4 av; av.x = xi0; av.y = xi1; av.z = xi2; av.w = ef;
        g_A[t * BB + i] = av;
        float4 mv; mv.x = m0; mv.y = m1; mv.z = m2;
        mv.w = __int_as_float(ridx | ((drt + 40) << 8));
        g_M[t * BB + i] = mv;

        fun += sCF[ridx] * DT_F;

        float dX20 = c1 * dB0, dX21 = c1 * dB1;
        float th_d = dX20 + 0.5f * PI_F;
        float sth, cth, sph, cph;
        __sincosf(th_d, &sth, &cth);
        __sincosf(dX21, &sph, &cph);
        float d30 = sth * cph - 1.0f;
        float d31 = sth * sph;
        float d32 = cth;
        float dX0 = T00 * d30 + T01 * d31 + T02 * d32;
        float dX1 = T10 * d30 + T11 * d31 + T12 * d32;
        float dX2 = T20 * d30 + T22 * d32;     // T21 = 0
        x0 += dX0; x1 += dX1; x2 += dX2;
        xi0 += dX0; xi1 += dX1; xi2 += sgn * dX2;
        rt += drt;
        if (xi2 < 0.f) { xi2 = -xi2; sgn = -sgn; }
    }

    float ef = __expf(-fun);
    out[BB + i] = (xi0 * xi0 + xi1 * xi1 + xi2 * xi2) / (float)rt * ef;
}

// ---------------- helpers ----------------
__device__ __forceinline__ void cp4s(float* dst, const float* __restrict__ src,
                                     int nfl, int tid) {
    const float4* s = (const float4*)src;
    float4* d = (float4*)dst;
    int n4 = nfl >> 2;
    for (int i = tid; i < n4; i += 256) d[i] = s[i];
}

// hardware tanh (MUFU.TANH, sm_75+): 1 instruction, max rel err ~2^-11
__device__ __forceinline__ float tanh_fast(float x) {
    float y;
    asm("tanh.approx.f32 %0, %1;" : "=f"(y) : "f"(x));
    return y;
}

// layer1: x(3) -> tanh(64); weights W1 @0 [3][64], b1 @192
__device__ __forceinline__ void layer1(const float* __restrict__ W,
                                       float x0, float x1, float x2, float* h1) {
#pragma unroll
    for (int j = 0; j < 64; j += 4) {
        float4 wa = *(const float4*)(W + j);
        float4 wb = *(const float4*)(W + 64 + j);
        float4 wc = *(const float4*)(W + 128 + j);
        float4 bb = *(const float4*)(W + 192 + j);
        h1[j + 0] = tanh_fast(fmaf(x0, wa.x, fmaf(x1, wb.x, fmaf(x2, wc.x, bb.x))));
        h1[j + 1] = tanh_fast(fmaf(x0, wa.y, fmaf(x1, wb.y, fmaf(x2, wc.y, bb.y))));
        h1[j + 2] = tanh_fast(fmaf(x0, wa.z, fmaf(x1, wb.z, fmaf(x2, wc.z, bb.z))));
        h1[j + 3] = tanh_fast(fmaf(x0, wa.w, fmaf(x1, wb.w, fmaf(x2, wc.w, bb.w))));
    }
}

// layer2 16-output pass via packed FFMA2: y[16] = tanh(h1 @ W2[:, cbase:cbase+16] + b2)
__device__ __forceinline__ void layer2_pass16(const float* __restrict__ W2,
                                              const float* __restrict__ b2,
                                              const float* __restrict__ h1,
                                              int cbase, float* y) {
    ull A[8];
    {
        const longlong2* bb = (const longlong2*)(b2 + cbase);
#pragma unroll
        for (int q = 0; q < 4; q++) {
            longlong2 v = bb[q];
            A[2 * q] = (ull)v.x; A[2 * q + 1] = (ull)v.y;
        }
    }
#pragma unroll
    for (int j = 0; j < 64; j++) {
        ull hp = pack2(h1[j], h1[j]);
        const longlong2* w = (const longlong2*)(W2 + j * 64 + cbase);
#pragma unroll
        for (int q = 0; q < 4; q++) {
            longlong2 wv = w[q];
            A[2 * q]     = fma2(hp, (ull)wv.x, A[2 * q]);
            A[2 * q + 1] = fma2(hp, (ull)wv.y, A[2 * q + 1]);
        }
    }
#pragma unroll
    for (int q = 0; q < 8; q++) {
        float2 f = unpk(A[q]);
        y[2 * q]     = tanh_fast(f.x);
        y[2 * q + 1] = tanh_fast(f.y);
    }
}

// ---------------- NN kernel: grid (NCH chunks, t) ----------------
// smem: gW 4416 | jW 4416 | E 7872 | B3E 128  = 16832 floats
#define SN_GW   0
#define SN_JW   4416
#define SN_E    8832
#define SN_B3E  16704
#define SN_TOT  16832
__global__ void __launch_bounds__(256, 2)
k_nn(const float* __restrict__ xt0, const int* __restrict__ rt0,
     const float* __restrict__ uW1, const float* __restrict__ ub1,
     const float* __restrict__ uW2, const float* __restrict__ ub2,
     const float* __restrict__ guW1, const float* __restrict__ gub1,
     const float* __restrict__ guW2, const float* __restrict__ gub2,
     const float* __restrict__ jxW1, const float* __restrict__ jxb1,
     const float* __restrict__ jxW2, const float* __restrict__ jxb2) {
    extern __shared__ float sm[];
    int t = blockIdx.y, tid = threadIdx.x;

    if (t < NSTEP) {
        cp4s(sm + SN_GW,        guW1 + t * 192,  192,  tid);
        cp4s(sm + SN_GW + 192,  gub1 + t * 64,   64,   tid);
        cp4s(sm + SN_GW + 256,  guW2 + t * 4096, 4096, tid);
        cp4s(sm + SN_GW + 4352, gub2 + t * 64,   64,   tid);
        cp4s(sm + SN_JW,        jxW1 + t * 192,  192,  tid);
        cp4s(sm + SN_JW + 192,  jxb1 + t * 64,   64,   tid);
        cp4s(sm + SN_JW + 256,  jxW2 + t * 4096, 4096, tid);
        cp4s(sm + SN_JW + 4352, jxb2 + t * 64,   64,   tid);
        const float* wsrc = g_W3Eg + (size_t)t * RR * 192;
        for (int idx = tid; idx < RR * 192; idx += 256) {
            int r = idx / 192, c = idx - r * 192;
            sm[SN_E + c * 41 + r] = wsrc[idx];
        }
        const float* bsrc = g_b3Eg + t * RR * 3;
        for (int idx = tid; idx < RR * 3; idx += 256) {
            int r = idx / 3, o = idx - r * 3;
            sm[SN_B3E + o * 41 + r] = bsrc[idx];
        }
    } else {
        cp4s(sm + SN_GW, uW1, 192, tid);
        cp4s(sm + SN_GW + 192, ub1, 64, tid);
        cp4s(sm + SN_GW + 256, uW2, 4096, tid);
        cp4s(sm + SN_GW + 4352, ub2, 64, tid);
        for (int idx = tid; idx < RR * 64; idx += 256) {
            int r = idx >> 6, j = idx & 63;
            sm[SN_E + j * 41 + r] = g_W3Eu[idx];
        }
        for (int idx = tid; idx < RR; idx += 256) sm[SN_B3E + idx] = g_b3Eu[idx];
    }
    __syncthreads();

    float h1[64];
    float y[16];

    if (t < NSTEP) {
#pragma unroll 1
        for (int k = 0; k < 8; k++) {
            int i = blockIdx.x * 256 + k * (NCH * 256) + tid;
            if (i >= BB) break;
            float4 av = g_A[t * BB + i];
            float4 mv = g_M[t * BB + i];
            int bits = __float_as_int(mv.w);
            int ridx = bits & 0xFF;
            int n = ridx * 81 + (bits >> 8);
            const float* crow = g_C + ((size_t)t * NPAD + n) * CROW;
            asm volatile("prefetch.global.L1 [%0];" :: "l"(crow));
            asm volatile("prefetch.global.L1 [%0];" :: "l"(crow + 32));
            asm volatile("prefetch.global.L1 [%0];" :: "l"(crow + 64));

            // ---- g-net ----
            layer1(sm + SN_GW, av.x, av.y, av.z, h1);
            float gu0 = sm[SN_B3E + ridx];
            float gu1 = sm[SN_B3E + 41 + ridx];
            float gu2 = sm[SN_B3E + 82 + ridx];
#pragma unroll 1
            for (int pass = 0; pass < 4; pass++) {
                layer2_pass16(sm + SN_GW + 256, sm + SN_GW + 4352, h1, pass * 16, y);
#pragma unroll
                for (int q = 0; q < 16; q++) {
                    const float* e = sm + SN_E + ((pass * 16 + q) * 3) * 41 + ridx;
                    gu0 = fmaf(y[q], e[0], gu0);
                    gu1 = fmaf(y[q], e[41], gu1);
                    gu2 = fmaf(y[q], e[82], gu2);
                }
            }

            // ---- j-net ----
            layer1(sm + SN_JW, av.x, av.y, av.z, h1);
            float jmp = crow[64];   // c0
            const float4* crow4 = (const float4*)crow;
#pragma unroll 1
            for (int pass = 0; pass < 4; pass++) {
                layer2_pass16(sm + SN_JW + 256, sm + SN_JW + 4352, h1, pass * 16, y);
                float4 c0 = crow4[pass * 4 + 0];
                float4 c1 = crow4[pass * 4 + 1];
                float4 c2 = crow4[pass * 4 + 2];
                float4 c3 = crow4[pass * 4 + 3];
                jmp = fmaf(y[0],  c0.x, jmp); jmp = fmaf(y[1],  c0.y, jmp);
                jmp = fmaf(y[2],  c0.z, jmp); jmp = fmaf(y[3],  c0.w, jmp);
                jmp = fmaf(y[4],  c1.x, jmp); jmp = fmaf(y[5],  c1.y, jmp);
                jmp = fmaf(y[6],  c1.z, jmp); jmp = fmaf(y[7],  c1.w, jmp);
                jmp = fmaf(y[8],  c2.x, jmp); jmp = fmaf(y[9],  c2.y, jmp);
                jmp = fmaf(y[10], c2.z, jmp); jmp = fmaf(y[11], c2.w, jmp);
                jmp = fmaf(y[12], c3.x, jmp); jmp = fmaf(y[13], c3.y, jmp);
                jmp = fmaf(y[14], c3.z, jmp); jmp = fmaf(y[15], c3.w, jmp);
            }

            g_part[t * BB + i] = gu0 * mv.x + gu1 * mv.y + gu2 * mv.z + av.w * jmp;
        }
    } else {
        // u0 slice
#pragma unroll 1
        for (int k = 0; k < 8; k++) {
            int i = blockIdx.x * 256 + k * (NCH * 256) + tid;
            if (i >= BB) break;
            float x0 = xt0[i * 3 + 0], x1 = xt0[i * 3 + 1], x2 = xt0[i * 3 + 2];
            int ridx = rt0[i] - RMIN;
            layer1(sm + SN_GW, x0, x1, x2, h1);
            float u = sm[SN_B3E + ridx];
#pragma unroll 1
            for (int pass = 0; pass < 4; pass++) {
                layer2_pass16(sm + SN_GW + 256, sm + SN_GW + 4352, h1, pass * 16, y);
#pragma unroll
                for (int q = 0; q < 16; q++)
                    u = fmaf(y[q], sm[SN_E + (pass * 16 + q) * 41 + ridx], u);
            }
            g_part[NSTEP * BB + i] = u;
        }
    }
}

// ---------------- reduction ----------------
__global__ void __launch_bounds__(256)
k_reduce(float* __restrict__ out) {
    int i = blockIdx.x * 256 + threadIdx.x;
    float s = g_part[NSTEP * BB + i];
#pragma unroll 1
    for (int t = 0; t < NSTEP; t++) s += g_part[t * BB + i];
    out[i] = s;
}

// ---------------- launcher ----------------
extern "C" void kernel_launch(void* const* d_in, const int* in_sizes, int n_in,
                              void* d_out, int out_size) {
    const int*   rt0    = (const int*)d_in[1];
    const float* xt0    = (const float*)d_in[2];
    const float* dBt    = (const float*)d_in[3];
    const float* u_jump = (const float*)d_in[4];
    const float* u_size = (const float*)d_in[5];
    const float* u_mc   = (const float*)d_in[6];
    const float* uW1 = (const float*)d_in[7];
    const float* ub1 = (const float*)d_in[8];
    const float* uW2 = (const float*)d_in[9];
    const float* ub2 = (const float*)d_in[10];
    const float* uW3 = (const float*)d_in[11];
    const float* ub3 = (const float*)d_in[12];
    const float* uE  = (const float*)d_in[13];
    const float* guW1 = (const float*)d_in[14];
    const float* gub1 = (const float*)d_in[15];
    const float* guW2 = (const float*)d_in[16];
    const float* gub2 = (const float*)d_in[17];
    const float* guW3 = (const float*)d_in[18];
    const float* gub3 = (const float*)d_in[19];
    const float* guE  = (const float*)d_in[20];
    const float* jxW1 = (const float*)d_in[21];
    const float* jxb1 = (const float*)d_in[22];
    const float* jxW2 = (const float*)d_in[23];
    const float* jxb2 = (const float*)d_in[24];
    const float* jxW3 = (const float*)d_in[25];
    const float* jxb3 = (const float*)d_in[26];
    const float* jump_r = (const float*)d_in[27];
    const float* jump_l = (const float*)d_in[28];
    float* out = (float*)d_out;

    cudaFuncSetAttribute(k_build_C, cudaFuncAttributeMaxDynamicSharedMemorySize,
                         SMEM_C_FLOATS * 4);
    cudaFuncSetAttribute(k_nn, cudaFuncAttributeMaxDynamicSharedMemorySize,
                         SN_TOT * 4);

    k_tables<<<1, 64>>>();
    k_mc_hist<<<(MCN * RR + 255) / 256, 256>>>(u_mc);
    k_mc_combine<<<(RR * PP + 127) / 128, 128>>>(jump_l);
    k_build_w3e<<<dim3((RR + RGRP - 1) / RGRP, NSTEP + 1), 256>>>(
        guW3, gub3, guE, uW3, ub3, uE);
    k_build_C<<<dim3(NBLK, NSTEP), 256, SMEM_C_FLOATS * 4>>>(jxW3, jxb3, jump_r, jump_l);
    k_geom<<<BB / 128, 128>>>(rt0, xt0, dBt, u_jump, u_size, out);
    k_nn<<<dim3(NCH, NSTEP + 1), 256, SN_TOT * 4>>>(
        xt0, rt0, uW1, ub1, uW2, ub2,
        guW1, gub1, guW2, gub2,
        jxW1, jxb1, jxW2, jxb2);
    k_reduce<<<BB / 256, 256>>>(out);
    (void)in_sizes; (void)n_in; (void)out_size;
}

// round 15
// speedup vs baseline: 1.2189x; 1.0510x over previous
#include <cuda_runtime.h>
#include <math.h>

#define RMIN 10
#define GAP  40
#define RR   41
#define PP   128
#define NSTEP 32
#define BB   16384
#define MCN  10000
#define DT_F 0.03125f
#define PI_F 3.14159265358979323846f
#define NPAD 3328       // 41*81 = 3321 padded
#define NBLK 52
#define CROW 68         // 64 coeffs + c0 + 3 pad
#define NCH  9          // k_nn sample chunks (9*33 = 297 blocks ~ 1 wave)
#define RGRP 6

typedef unsigned long long ull;

// ---------------- f32x2 packed helpers ----------------
__device__ __forceinline__ ull pack2(float lo, float hi) {
    ull r;
    asm("mov.b64 %0, {%1, %2};" : "=l"(r) : "f"(lo), "f"(hi));
    return r;
}
__device__ __forceinline__ ull fma2(ull a, ull b, ull c) {
    ull d;
    asm("fma.rn.f32x2 %0, %1, %2, %3;" : "=l"(d) : "l"(a), "l"(b), "l"(c));
    return d;
}
__device__ __forceinline__ float2 unpk(ull v) {
    float2 f;
    asm("mov.b64 {%0, %1}, %2;" : "=f"(f.x), "=f"(f.y) : "l"(v));
    return f;
}

// ---------------- device scratch ----------------
__device__ float g_jm[RR * 80];
__device__ float g_cr[RR];
__device__ float g_cfr[RR];
__device__ int   g_hist[RR * 80];
__device__ float g_mcjump[RR * PP];
__device__ float g_W3Eu[RR * 64];
__device__ float g_b3Eu[RR];
__device__ float g_W3Eg[NSTEP * RR * 192];
__device__ float g_b3Eg[NSTEP * RR * 3];
__device__ float g_C[(size_t)NSTEP * NPAD * CROW];   // ~29 MB
__device__ float4 g_A[NSTEP * BB];                   // xi0,xi1,xi2, ef
__device__ float4 g_M[NSTEP * BB];                   // m0,m1,m2, bits(ridx|d<<8)
__device__ float  g_part[(NSTEP + 1) * BB];

// upper bound on non-decreasing 80-row: #(row[j] <= u)
__device__ __forceinline__ int ubound80(const float* __restrict__ row, float u) {
    int lo = 0, hi = 80;
    while (lo < hi) {
        int mid = (lo + hi) >> 1;
        if (row[mid] <= u) lo = mid + 1; else hi = mid;
    }
    return lo;
}

// ---------------- tables (+ hist zero) ----------------
__global__ void k_tables() {
    int tid = threadIdx.x;
    for (int i = tid; i < RR * 80; i += 64) g_hist[i] = 0;
    int r = tid;
    if (r >= RR) return;
    float cum = 0.f, slam = 0.f, smu = 0.f;
    for (int k = 1; k <= GAP; k++) {
        float kk = (float)k;
        float lam = ((r + RMIN + k) <= RMIN + GAP) ? 1.0f / (kk * kk) : 0.0f;
        slam += lam; cum += lam;
        g_jm[r * 80 + (k - 1)] = cum;
    }
    for (int k = 1; k <= GAP; k++) {
        float kk = (float)k;
        float mu = ((r + RMIN - k) >= RMIN) ? 1.0f / (kk * kk) : 0.0f;
        smu += mu; cum += mu;
        g_jm[r * 80 + GAP + (k - 1)] = cum;
    }
    g_cr[r] = cum;
    g_cfr[r] = slam + smu - cum;
    for (int j = 0; j < 80; j++) g_jm[r * 80 + j] /= cum;
}

__global__ void k_mc_hist(const float* __restrict__ u_mc) {
    int i = blockIdx.x * blockDim.x + threadIdx.x;
    if (i >= MCN * RR) return;
    int r = i % RR;
    int ind = ubound80(&g_jm[r * 80], u_mc[i]);
    atomicAdd(&g_hist[r * 80 + ind], 1);
}

__global__ void k_mc_combine(const float* __restrict__ jump_l) {
    int idx = blockIdx.x * blockDim.x + threadIdx.x;
    if (idx >= RR * PP) return;
    int r = idx / PP, p = idx % PP;
    float s = 0.f;
    for (int b = 0; b < 80; b++) {
        int c = g_hist[r * 80 + b];
        if (c) s += (float)c * jump_l[b * PP + p];
    }
    g_mcjump[idx] = s * (1.0f / (float)MCN) * g_cr[r];
}

// ---------------- W3E build: one CTA per (r-group of 6, t); t=NSTEP -> u-net ----------------
__global__ void __launch_bounds__(256, 1)
k_build_w3e(const float* __restrict__ guW3, const float* __restrict__ gub3,
            const float* __restrict__ guE,
            const float* __restrict__ uW3, const float* __restrict__ ub3,
            const float* __restrict__ uE) {
    __shared__ float sW[64 * 129];
    __shared__ float sE6[RGRP * 384];
    int rb = blockIdx.x * RGRP, t = blockIdx.y, tid = threadIdx.x;
    int nr = (RR - rb < RGRP) ? (RR - rb) : RGRP;
    if (t < NSTEP) {
        for (int idx = tid; idx < 8192; idx += 256) {
            int j = idx >> 7, p = idx & 127;
            sW[j * 129 + p] = guW3[(size_t)t * 8192 + idx];
        }
        for (int idx = tid; idx < nr * 384; idx += 256)
            sE6[idx] = guE[((size_t)t * RR + rb) * 384 + idx];
        __syncthreads();
        for (int idx = tid; idx < nr * 192; idx += 256) {
            int rr = idx / 192, c = idx - rr * 192;
            int j = c & 63, o = c >> 6;
            const float* w = sW + j * 129;
            const float* e = sE6 + rr * 384 + o;
            float acc = 0.f;
#pragma unroll 8
            for (int p = 0; p < 128; p++) acc = fmaf(w[p], e[p * 3], acc);
            g_W3Eg[((size_t)t * RR + rb + rr) * 192 + j * 3 + o] = acc;
        }
        if (tid < nr * 3) {
            int rr = tid / 3, o = tid - rr * 3;
            const float* b = gub3 + t * 128;
            const float* e = sE6 + rr * 384 + o;
            float a = 0.f;
#pragma unroll 8
            for (int p = 0; p < 128; p++) a = fmaf(b[p], e[p * 3], a);
            g_b3Eg[(t * RR + rb + rr) * 3 + o] = a;
        }
    } else {
        for (int idx = tid; idx < 8192; idx += 256) {
            int j = idx >> 7, p = idx & 127;
            sW[j * 129 + p] = uW3[idx];
        }
        for (int idx = tid; idx < nr * 128; idx += 256) sE6[idx] = uE[rb * 128 + idx];
        __syncthreads();
        for (int idx = tid; idx < nr * 64; idx += 256) {
            int rr = idx >> 6, j = idx & 63;
            const float* w = sW + j * 129;
            const float* e = sE6 + rr * 128;
            float acc = 0.f;
#pragma unroll 8
            for (int p = 0; p < 128; p++) acc = fmaf(w[p], e[p], acc);
            g_W3Eu[(rb + rr) * 64 + j] = acc;
        }
        if (tid < nr) {
            const float* e = sE6 + tid * 128;
            float acc = 0.f;
#pragma unroll 8
            for (int p = 0; p < 128; p++) acc = fmaf(ub3[p], e[p], acc);
            g_b3Eu[rb + tid] = acc;
        }
    }
}

// ---------------- C table build: FFMA2 + coalesced float4 stores ----------------
#define CPAD 68
#define SMEM_C_FLOATS (2 * 128 * CPAD)
__global__ void __launch_bounds__(256, 1)
k_build_C(const float* __restrict__ jxW3, const float* __restrict__ jxb3,
          const float* __restrict__ jump_r, const float* __restrict__ jump_l) {
    extern __shared__ float smc[];
    float* smA = smc;                 // [128][68]: smA[p][j]
    float* smB = smc + 128 * CPAD;    // [128][68]: smB[p][n]
    int nblk = blockIdx.x, t = blockIdx.y, tid = threadIdx.x;

    for (int idx = tid; idx < 8192; idx += 256) {
        int j = idx >> 7, p = idx & 127;
        smA[p * CPAD + j] = jxW3[(size_t)t * 8192 + idx];
    }
    for (int idx = tid; idx < 8192; idx += 256) {
        int n = idx >> 7, p = idx & 127;
        int n_g = nblk * 64 + n;
        float b = 0.f;
        if (n_g < RR * 81) {
            int r = n_g / 81, d = n_g - r * 81;
            float jl = 0.f;
            if (d > 40)      jl = jump_l[(d - 41) * PP + p];
            else if (d < 40) jl = jump_l[(79 - d) * PP + p];
            b = jump_r[r * PP + p] * (jl - g_mcjump[r * PP + p] * DT_F);
        }
        smB[p * CPAD + n] = b;
    }
    __syncthreads();

    int tx = tid & 15, ty = tid >> 4;
    ull acc[4][2];
#pragma unroll
    for (int n = 0; n < 4; n++) { acc[n][0] = 0ull; acc[n][1] = 0ull; }
#pragma unroll 4
    for (int p = 0; p < 128; p++) {
        longlong2 aj = *(const longlong2*)(smA + p * CPAD + tx * 4);
        float4 bn = *(const float4*)(smB + p * CPAD + ty * 4);
        ull b0 = pack2(bn.x, bn.x), b1 = pack2(bn.y, bn.y);
        ull b2 = pack2(bn.z, bn.z), b3 = pack2(bn.w, bn.w);
        acc[0][0] = fma2(b0, (ull)aj.x, acc[0][0]);
        acc[0][1] = fma2(b0, (ull)aj.y, acc[0][1]);
        acc[1][0] = fma2(b1, (ull)aj.x, acc[1][0]);
        acc[1][1] = fma2(b1, (ull)aj.y, acc[1][1]);
        acc[2][0] = fma2(b2, (ull)aj.x, acc[2][0]);
        acc[2][1] = fma2(b2, (ull)aj.y, acc[2][1]);
        acc[3][0] = fma2(b3, (ull)aj.x, acc[3][0]);
        acc[3][1] = fma2(b3, (ull)aj.y, acc[3][1]);
    }
#pragma unroll
    for (int n = 0; n < 4; n++) {
        int n_g = nblk * 64 + ty * 4 + n;
        float2 lo = unpk(acc[n][0]);
        float2 hi = unpk(acc[n][1]);
        float4 v; v.x = lo.x; v.y = lo.y; v.z = hi.x; v.w = hi.y;
        *(float4*)(g_C + ((size_t)t * NPAD + n_g) * CROW + tx * 4) = v;
    }
    if (tid < 64) {
        int n_g = nblk * 64 + tid;
        const float* b3 = jxb3 + t * 128;
        float c0 = 0.f;
#pragma unroll 4
        for (int p = 0; p < 128; p++) c0 = fmaf(b3[p], smB[p * CPAD + tid], c0);
        size_t base = ((size_t)t * NPAD + n_g) * CROW;
        g_C[base + 64] = c0;
        g_C[base + 65] = 0.f; g_C[base + 66] = 0.f; g_C[base + 67] = 0.f;
    }
}

// ---------------- geometry pass: trajectory only, NN-free ----------------
__global__ void __launch_bounds__(128)
k_geom(const int* __restrict__ rt0, const float* __restrict__ xt0,
       const float* __restrict__ dBt, const float* __restrict__ u_jump,
       const float* __restrict__ u_size, float* __restrict__ out) {
    __shared__ float sJM[RR * 80];
    __shared__ float sCR[RR];
    __shared__ float sCF[RR];
    int tid = threadIdx.x;
    for (int idx = tid; idx < RR * 80; idx += 128) sJM[idx] = g_jm[idx];
    for (int idx = tid; idx < RR; idx += 128) {
        sCR[idx] = g_cr[idx];
        sCF[idx] = g_cfr[idx];
    }
    __syncthreads();

    int i = blockIdx.x * 128 + tid;
    const float sqDT = 0.17677669529663688985f;   // sqrt(1/32)
    const float sq2D = 1.41421356237309504880f;   // sqrt(2)
    int rt = rt0[i];
    float x0 = xt0[i * 3 + 0], x1 = xt0[i * 3 + 1], x2 = xt0[i * 3 + 2];
    float xi0 = x0, xi1 = x1, xi2 = x2;
    float sgn = 1.f, fun = 0.f;

#pragma unroll 1
    for (int t = 0; t < NSTEP; t++) {
        int ridx = rt - RMIN;
        float uj = u_jump[t * BB + i];
        int drt = 0;
        if (uj < sCR[ridx] * DT_F) {
            int ind = ubound80(sJM + ridx * 80, u_size[t * BB + i]);
            drt = (ind < GAP) ? (ind + 1) : -(ind - GAP + 1);
        }

        float rn = sqrtf(x0 * x0 + x1 * x1 + x2 * x2);
        float cz = fminf(fmaxf(x2 / rn, -1.0f), 1.0f);
        float theta = acosf(cz) - 0.5f * PI_F;
        float phi = atan2f(x1, x0);
        float st, ct, sp, cpv;
        __sincosf(theta, &st, &ct);
        __sincosf(phi, &sp, &cpv);
        float T00 = cpv * ct, T01 = -sp,  T02 = cpv * st;
        float T10 = sp * ct,  T11 = cpv,  T12 = sp * st;
        float T20 = -st,      T22 = ct;

        float2 db = ((const float2*)dBt)[t * BB + i];
        float dB0 = db.x * sqDT, dB1 = db.y * sqDT;
        float rtf = (float)rt;
        float c1 = sq2D / rtf;
        float ef = __expf(-fun);

        float m0 = ef * c1 * (T01 * dB1 - T02 * dB0);
        float m1 = ef * c1 * (T11 * dB1 - T12 * dB0);
        float m2 = -ef * c1 * sgn * T22 * dB0;
        float4 av; av.x = xi0; av.y = xi1; av.z = xi2; av.w = ef;
        g_A[t * BB + i] = av;
        float4 mv; mv.x = m0; mv.y = m1; mv.z = m2;
        mv.w = __int_as_float(ridx | ((drt + 40) << 8));
        g_M[t * BB + i] = mv;

        fun += sCF[ridx] * DT_F;

        float dX20 = c1 * dB0, dX21 = c1 * dB1;
        float th_d = dX20 + 0.5f * PI_F;
        float sth, cth, sph, cph;
        __sincosf(th_d, &sth, &cth);
        __sincosf(dX21, &sph, &cph);
        float d30 = sth * cph - 1.0f;
        float d31 = sth * sph;
        float d32 = cth;
        float dX0 = T00 * d30 + T01 * d31 + T02 * d32;
        float dX1 = T10 * d30 + T11 * d31 + T12 * d32;
        float dX2 = T20 * d30 + T22 * d32;     // T21 = 0
        x0 += dX0; x1 += dX1; x2 += dX2;
        xi0 += dX0; xi1 += dX1; xi2 += sgn * dX2;
        rt += drt;
        if (xi2 < 0.f) { xi2 = -xi2; sgn = -sgn; }
    }

    float ef = __expf(-fun);
    out[BB + i] = (xi0 * xi0 + xi1 * xi1 + xi2 * xi2) / (float)rt * ef;
}

// ---------------- helpers ----------------
__device__ __forceinline__ void cp4s(float* dst, const float* __restrict__ src,
                                     int nfl, int tid) {
    const float4* s = (const float4*)src;
    float4* d = (float4*)dst;
    int n4 = nfl >> 2;
    for (int i = tid; i < n4; i += 256) d[i] = s[i];
}

// hardware tanh (MUFU.TANH, sm_75+)
__device__ __forceinline__ float tanh_fast(float x) {
    float y;
    asm("tanh.approx.f32 %0, %1;" : "=f"(y) : "f"(x));
    return y;
}

// layer1: x(3) -> tanh(64); weights W1 @0 [3][64], b1 @192
__device__ __forceinline__ void layer1(const float* __restrict__ W,
                                       float x0, float x1, float x2, float* h1) {
#pragma unroll
    for (int j = 0; j < 64; j += 4) {
        float4 wa = *(const float4*)(W + j);
        float4 wb = *(const float4*)(W + 64 + j);
        float4 wc = *(const float4*)(W + 128 + j);
        float4 bb = *(const float4*)(W + 192 + j);
        h1[j + 0] = tanh_fast(fmaf(x0, wa.x, fmaf(x1, wb.x, fmaf(x2, wc.x, bb.x))));
        h1[j + 1] = tanh_fast(fmaf(x0, wa.y, fmaf(x1, wb.y, fmaf(x2, wc.y, bb.y))));
        h1[j + 2] = tanh_fast(fmaf(x0, wa.z, fmaf(x1, wb.z, fmaf(x2, wc.z, bb.z))));
        h1[j + 3] = tanh_fast(fmaf(x0, wa.w, fmaf(x1, wb.w, fmaf(x2, wc.w, bb.w))));
    }
}

// layer2 16-output pass via packed FFMA2: y[16] = tanh(h1 @ W2[:, cbase:cbase+16] + b2)
__device__ __forceinline__ void layer2_pass16(const float* __restrict__ W2,
                                              const float* __restrict__ b2,
                                              const float* __restrict__ h1,
                                              int cbase, float* y) {
    ull A[8];
    {
        const longlong2* bb = (const longlong2*)(b2 + cbase);
#pragma unroll
        for (int q = 0; q < 4; q++) {
            longlong2 v = bb[q];
            A[2 * q] = (ull)v.x; A[2 * q + 1] = (ull)v.y;
        }
    }
#pragma unroll
    for (int j = 0; j < 64; j++) {
        ull hp = pack2(h1[j], h1[j]);
        const longlong2* w = (const longlong2*)(W2 + j * 64 + cbase);
#pragma unroll
        for (int q = 0; q < 4; q++) {
            longlong2 wv = w[q];
            A[2 * q]     = fma2(hp, (ull)wv.x, A[2 * q]);
            A[2 * q + 1] = fma2(hp, (ull)wv.y, A[2 * q + 1]);
        }
    }
#pragma unroll
    for (int q = 0; q < 8; q++) {
        float2 f = unpk(A[q]);
        y[2 * q]     = tanh_fast(f.x);
        y[2 * q + 1] = tanh_fast(f.y);
    }
}

// ---------------- NN kernel: grid (NCH chunks, t) ----------------
// smem: gW 4416 | jW 4416 | E 7872 | B3E 128  = 16832 floats
#define SN_GW   0
#define SN_JW   4416
#define SN_E    8832
#define SN_B3E  16704
#define SN_TOT  16832
__global__ void __launch_bounds__(256, 2)
k_nn(const float* __restrict__ xt0, const int* __restrict__ rt0,
     const float* __restrict__ uW1, const float* __restrict__ ub1,
     const float* __restrict__ uW2, const float* __restrict__ ub2,
     const float* __restrict__ guW1, const float* __restrict__ gub1,
     const float* __restrict__ guW2, const float* __restrict__ gub2,
     const float* __restrict__ jxW1, const float* __restrict__ jxb1,
     const float* __restrict__ jxW2, const float* __restrict__ jxb2) {
    extern __shared__ float sm[];
    int t = blockIdx.y, tid = threadIdx.x;

    if (t < NSTEP) {
        cp4s(sm + SN_GW,        guW1 + t * 192,  192,  tid);
        cp4s(sm + SN_GW + 192,  gub1 + t * 64,   64,   tid);
        cp4s(sm + SN_GW + 256,  guW2 + t * 4096, 4096, tid);
        cp4s(sm + SN_GW + 4352, gub2 + t * 64,   64,   tid);
        cp4s(sm + SN_JW,        jxW1 + t * 192,  192,  tid);
        cp4s(sm + SN_JW + 192,  jxb1 + t * 64,   64,   tid);
        cp4s(sm + SN_JW + 256,  jxW2 + t * 4096, 4096, tid);
        cp4s(sm + SN_JW + 4352, jxb2 + t * 64,   64,   tid);
        const float* wsrc = g_W3Eg + (size_t)t * RR * 192;
        for (int idx = tid; idx < RR * 192; idx += 256) {
            int r = idx / 192, c = idx - r * 192;
            sm[SN_E + c * 41 + r] = wsrc[idx];
        }
        const float* bsrc = g_b3Eg + t * RR * 3;
        for (int idx = tid; idx < RR * 3; idx += 256) {
            int r = idx / 3, o = idx - r * 3;
            sm[SN_B3E + o * 41 + r] = bsrc[idx];
        }
    } else {
        cp4s(sm + SN_GW, uW1, 192, tid);
        cp4s(sm + SN_GW + 192, ub1, 64, tid);
        cp4s(sm + SN_GW + 256, uW2, 4096, tid);
        cp4s(sm + SN_GW + 4352, ub2, 64, tid);
        for (int idx = tid; idx < RR * 64; idx += 256) {
            int r = idx >> 6, j = idx & 63;
            sm[SN_E + j * 41 + r] = g_W3Eu[idx];
        }
        for (int idx = tid; idx < RR; idx += 256) sm[SN_B3E + idx] = g_b3Eu[idx];
    }
    __syncthreads();

    float h1[64];
    float y[16];

    if (t < NSTEP) {
#pragma unroll 1
        for (int k = 0; k < 8; k++) {
            int i = blockIdx.x * 256 + k * (NCH * 256) + tid;
            if (i >= BB) break;
            float4 av = g_A[t * BB + i];
            float4 mv = g_M[t * BB + i];
            int bits = __float_as_int(mv.w);
            int ridx = bits & 0xFF;
            int n = ridx * 81 + (bits >> 8);
            const float* crow = g_C + ((size_t)t * NPAD + n) * CROW;
            asm volatile("prefetch.global.L1 [%0];" :: "l"(crow));
            asm volatile("prefetch.global.L1 [%0];" :: "l"(crow + 32));
            asm volatile("prefetch.global.L1 [%0];" :: "l"(crow + 64));

            // ---- g-net ----
            layer1(sm + SN_GW, av.x, av.y, av.z, h1);
            float gu0 = sm[SN_B3E + ridx];
            float gu1 = sm[SN_B3E + 41 + ridx];
            float gu2 = sm[SN_B3E + 82 + ridx];
#pragma unroll 1
            for (int pass = 0; pass < 4; pass++) {
                layer2_pass16(sm + SN_GW + 256, sm + SN_GW + 4352, h1, pass * 16, y);
#pragma unroll
                for (int q = 0; q < 16; q++) {
                    const float* e = sm + SN_E + ((pass * 16 + q) * 3) * 41 + ridx;
                    gu0 = fmaf(y[q], e[0], gu0);
                    gu1 = fmaf(y[q], e[41], gu1);
                    gu2 = fmaf(y[q], e[82], gu2);
                }
            }

            // ---- j-net ----
            layer1(sm + SN_JW, av.x, av.y, av.z, h1);
            float jmp = crow[64];   // c0
            const float4* crow4 = (const float4*)crow;
#pragma unroll 1
            for (int pass = 0; pass < 4; pass++) {
                layer2_pass16(sm + SN_JW + 256, sm + SN_JW + 4352, h1, pass * 16, y);
                float4 c0 = crow4[pass * 4 + 0];
                float4 c1 = crow4[pass * 4 + 1];
                float4 c2 = crow4[pass * 4 + 2];
                float4 c3 = crow4[pass * 4 + 3];
                jmp = fmaf(y[0],  c0.x, jmp); jmp = fmaf(y[1],  c0.y, jmp);
                jmp = fmaf(y[2],  c0.z, jmp); jmp = fmaf(y[3],  c0.w, jmp);
                jmp = fmaf(y[4],  c1.x, jmp); jmp = fmaf(y[5],  c1.y, jmp);
                jmp = fmaf(y[6],  c1.z, jmp); jmp = fmaf(y[7],  c1.w, jmp);
                jmp = fmaf(y[8],  c2.x, jmp); jmp = fmaf(y[9],  c2.y, jmp);
                jmp = fmaf(y[10], c2.z, jmp); jmp = fmaf(y[11], c2.w, jmp);
                jmp = fmaf(y[12], c3.x, jmp); jmp = fmaf(y[13], c3.y, jmp);
                jmp = fmaf(y[14], c3.z, jmp); jmp = fmaf(y[15], c3.w, jmp);
            }

            g_part[t * BB + i] = gu0 * mv.x + gu1 * mv.y + gu2 * mv.z + av.w * jmp;
        }
    } else {
        // u0 slice
#pragma unroll 1
        for (int k = 0; k < 8; k++) {
            int i = blockIdx.x * 256 + k * (NCH * 256) + tid;
            if (i >= BB) break;
            float x0 = xt0[i * 3 + 0], x1 = xt0[i * 3 + 1], x2 = xt0[i * 3 + 2];
            int ridx = rt0[i] - RMIN;
            layer1(sm + SN_GW, x0, x1, x2, h1);
            float u = sm[SN_B3E + ridx];
#pragma unroll 1
            for (int pass = 0; pass < 4; pass++) {
                layer2_pass16(sm + SN_GW + 256, sm + SN_GW + 4352, h1, pass * 16, y);
#pragma unroll
                for (int q = 0; q < 16; q++)
                    u = fmaf(y[q], sm[SN_E + (pass * 16 + q) * 41 + ridx], u);
            }
            g_part[NSTEP * BB + i] = u;
        }
    }
}

// ---------------- reduction ----------------
__global__ void __launch_bounds__(256)
k_reduce(float* __restrict__ out) {
    int i = blockIdx.x * 256 + threadIdx.x;
    float s = g_part[NSTEP * BB + i];
#pragma unroll 1
    for (int t = 0; t < NSTEP; t++) s += g_part[t * BB + i];
    out[i] = s;
}

// ---------------- launcher (multi-stream fork/join, capture-legal) ----------------
extern "C" void kernel_launch(void* const* d_in, const int* in_sizes, int n_in,
                              void* d_out, int out_size) {
    const int*   rt0    = (const int*)d_in[1];
    const float* xt0    = (const float*)d_in[2];
    const float* dBt    = (const float*)d_in[3];
    const float* u_jump = (const float*)d_in[4];
    const float* u_size = (const float*)d_in[5];
    const float* u_mc   = (const float*)d_in[6];
    const float* uW1 = (const float*)d_in[7];
    const float* ub1 = (const float*)d_in[8];
    const float* uW2 = (const float*)d_in[9];
    const float* ub2 = (const float*)d_in[10];
    const float* uW3 = (const float*)d_in[11];
    const float* ub3 = (const float*)d_in[12];
    const float* uE  = (const float*)d_in[13];
    const float* guW1 = (const float*)d_in[14];
    const float* gub1 = (const float*)d_in[15];
    const float* guW2 = (const float*)d_in[16];
    const float* gub2 = (const float*)d_in[17];
    const float* guW3 = (const float*)d_in[18];
    const float* gub3 = (const float*)d_in[19];
    const float* guE  = (const float*)d_in[20];
    const float* jxW1 = (const float*)d_in[21];
    const float* jxb1 = (const float*)d_in[22];
    const float* jxW2 = (const float*)d_in[23];
    const float* jxb2 = (const float*)d_in[24];
    const float* jxW3 = (const float*)d_in[25];
    const float* jxb3 = (const float*)d_in[26];
    const float* jump_r = (const float*)d_in[27];
    const float* jump_l = (const float*)d_in[28];
    float* out = (float*)d_out;

    // lazily-created side streams + events (host objects, no device memory;
    // created on the first, uncaptured, correctness call)
    static cudaStream_t sA = 0, sB = 0;
    static cudaEvent_t evStart = 0, evTab = 0, evA = 0, evB = 0;
    if (sA == 0) {
        cudaStreamCreateWithFlags(&sA, cudaStreamNonBlocking);
        cudaStreamCreateWithFlags(&sB, cudaStreamNonBlocking);
        cudaEventCreateWithFlags(&evStart, cudaEventDisableTiming);
        cudaEventCreateWithFlags(&evTab, cudaEventDisableTiming);
        cudaEventCreateWithFlags(&evA, cudaEventDisableTiming);
        cudaEventCreateWithFlags(&evB, cudaEventDisableTiming);
    }

    cudaFuncSetAttribute(k_build_C, cudaFuncAttributeMaxDynamicSharedMemorySize,
                         SMEM_C_FLOATS * 4);
    cudaFuncSetAttribute(k_nn, cudaFuncAttributeMaxDynamicSharedMemorySize,
                         SN_TOT * 4);

    // fork sA at start: w3e depends only on kernel inputs
    cudaEventRecord(evStart, 0);
    cudaStreamWaitEvent(sA, evStart, 0);
    k_build_w3e<<<dim3((RR + RGRP - 1) / RGRP, NSTEP + 1), 256, 0, sA>>>(
        guW3, gub3, guE, uW3, ub3, uE);
    cudaEventRecord(evA, sA);

    // main stream: tables -> mc chain -> build_C
    k_tables<<<1, 64>>>();
    // fork sB after tables: geom needs g_jm/g_cr/g_cfr only
    cudaEventRecord(evTab, 0);
    cudaStreamWaitEvent(sB, evTab, 0);
    k_geom<<<BB / 128, 128, 0, sB>>>(rt0, xt0, dBt, u_jump, u_size, out);
    cudaEventRecord(evB, sB);

    k_mc_hist<<<(MCN * RR + 255) / 256, 256>>>(u_mc);
    k_mc_combine<<<(RR * PP + 127) / 128, 128>>>(jump_l);
    k_build_C<<<dim3(NBLK, NSTEP), 256, SMEM_C_FLOATS * 4>>>(jxW3, jxb3, jump_r, jump_l);

    // join: k_nn needs w3e outputs, geom outputs, and C table
    cudaStreamWaitEvent(0, evA, 0);
    cudaStreamWaitEvent(0, evB, 0);
    k_nn<<<dim3(NCH, NSTEP + 1), 256, SN_TOT * 4>>>(
        xt0, rt0, uW1, ub1, uW2, ub2,
        guW1, gub1, guW2, gub2,
        jxW1, jxb1, jxW2, jxb2);
    k_reduce<<<BB / 256, 256>>>(out);
    (void)in_sizes; (void)n_in; (void)out_size;
}

// round 16
// speedup vs baseline: 1.2248x; 1.0048x over previous
#include <cuda_runtime.h>
#include <math.h>

#define RMIN 10
#define GAP  40
#define RR   41
#define PP   128
#define NSTEP 32
#define BB   16384
#define MCN  10000
#define DT_F 0.03125f
#define PI_F 3.14159265358979323846f
#define NPAD 3328       // 41*81 = 3321 padded
#define NBLK 52
#define CROW 68         // 64 coeffs + c0 + 3 pad
#define NCH  9          // k_nn sample chunks (9*33 = 297 blocks ~ 1 wave)
#define RGRP 6
#define MCH_BLOCKS 64

typedef unsigned long long ull;

// ---------------- f32x2 packed helpers ----------------
__device__ __forceinline__ ull pack2(float lo, float hi) {
    ull r;
    asm("mov.b64 %0, {%1, %2};" : "=l"(r) : "f"(lo), "f"(hi));
    return r;
}
__device__ __forceinline__ ull fma2(ull a, ull b, ull c) {
    ull d;
    asm("fma.rn.f32x2 %0, %1, %2, %3;" : "=l"(d) : "l"(a), "l"(b), "l"(c));
    return d;
}
__device__ __forceinline__ float2 unpk(ull v) {
    float2 f;
    asm("mov.b64 {%0, %1}, %2;" : "=f"(f.x), "=f"(f.y) : "l"(v));
    return f;
}

// ---------------- device scratch ----------------
__device__ float g_jm[RR * 80];
__device__ float g_cr[RR];
__device__ float g_cfr[RR];
__device__ int   g_hist[RR * 80];
__device__ float g_mcjump[RR * PP];
__device__ float g_W3Eu[RR * 64];
__device__ float g_b3Eu[RR];
__device__ float g_W3Eg[NSTEP * RR * 192];
__device__ float g_b3Eg[NSTEP * RR * 3];
__device__ float g_C[(size_t)NSTEP * NPAD * CROW];   // ~29 MB
__device__ float4 g_A[NSTEP * BB];                   // xi0,xi1,xi2, ef
__device__ float4 g_M[NSTEP * BB];                   // m0,m1,m2, bits(ridx|d<<8)
__device__ float  g_part[(NSTEP + 1) * BB];

// upper bound on non-decreasing 80-row: #(row[j] <= u)
__device__ __forceinline__ int ubound80(const float* __restrict__ row, float u) {
    int lo = 0, hi = 80;
    while (lo < hi) {
        int mid = (lo + hi) >> 1;
        if (row[mid] <= u) lo = mid + 1; else hi = mid;
    }
    return lo;
}

// ---------------- tables (+ hist zero) ----------------
__global__ void k_tables() {
    int tid = threadIdx.x;
    for (int i = tid; i < RR * 80; i += 64) g_hist[i] = 0;
    int r = tid;
    if (r >= RR) return;
    float cum = 0.f, slam = 0.f, smu = 0.f;
    for (int k = 1; k <= GAP; k++) {
        float kk = (float)k;
        float lam = ((r + RMIN + k) <= RMIN + GAP) ? 1.0f / (kk * kk) : 0.0f;
        slam += lam; cum += lam;
        g_jm[r * 80 + (k - 1)] = cum;
    }
    for (int k = 1; k <= GAP; k++) {
        float kk = (float)k;
        float mu = ((r + RMIN - k) >= RMIN) ? 1.0f / (kk * kk) : 0.0f;
        smu += mu; cum += mu;
        g_jm[r * 80 + GAP + (k - 1)] = cum;
    }
    g_cr[r] = cum;
    g_cfr[r] = slam + smu - cum;
    for (int j = 0; j < 80; j++) g_jm[r * 80 + j] /= cum;
}

// MC hist: smem-staged jm + smem histogram, one merge per block
__global__ void __launch_bounds__(256)
k_mc_hist(const float* __restrict__ u_mc) {
    __shared__ float sJM[RR * 80];
    __shared__ int   sH[RR * 80];
    int tid = threadIdx.x;
    for (int idx = tid; idx < RR * 80; idx += 256) {
        sJM[idx] = g_jm[idx];
        sH[idx] = 0;
    }
    __syncthreads();
    for (int i = blockIdx.x * 256 + tid; i < MCN * RR; i += MCH_BLOCKS * 256) {
        int r = i % RR;
        int ind = ubound80(sJM + r * 80, u_mc[i]);
        atomicAdd(&sH[r * 80 + ind], 1);
    }
    __syncthreads();
    for (int idx = tid; idx < RR * 80; idx += 256) {
        int v = sH[idx];
        if (v) atomicAdd(&g_hist[idx], v);
    }
}

__global__ void k_mc_combine(const float* __restrict__ jump_l) {
    int idx = blockIdx.x * blockDim.x + threadIdx.x;
    if (idx >= RR * PP) return;
    int r = idx / PP, p = idx % PP;
    float s = 0.f;
    for (int b = 0; b < 80; b++) {
        int c = g_hist[r * 80 + b];
        if (c) s += (float)c * jump_l[b * PP + p];
    }
    g_mcjump[idx] = s * (1.0f / (float)MCN) * g_cr[r];
}

// ---------------- W3E build: one CTA per (r-group of 6, t); t=NSTEP -> u-net ----------------
__global__ void __launch_bounds__(256, 1)
k_build_w3e(const float* __restrict__ guW3, const float* __restrict__ gub3,
            const float* __restrict__ guE,
            const float* __restrict__ uW3, const float* __restrict__ ub3,
            const float* __restrict__ uE) {
    __shared__ float sW[64 * 129];
    __shared__ float sE6[RGRP * 384];
    int rb = blockIdx.x * RGRP, t = blockIdx.y, tid = threadIdx.x;
    int nr = (RR - rb < RGRP) ? (RR - rb) : RGRP;
    if (t < NSTEP) {
        for (int idx = tid; idx < 8192; idx += 256) {
            int j = idx >> 7, p = idx & 127;
            sW[j * 129 + p] = guW3[(size_t)t * 8192 + idx];
        }
        for (int idx = tid; idx < nr * 384; idx += 256)
            sE6[idx] = guE[((size_t)t * RR + rb) * 384 + idx];
        __syncthreads();
        for (int idx = tid; idx < nr * 192; idx += 256) {
            int rr = idx / 192, c = idx - rr * 192;
            int j = c & 63, o = c >> 6;
            const float* w = sW + j * 129;
            const float* e = sE6 + rr * 384 + o;
            float acc = 0.f;
#pragma unroll 8
            for (int p = 0; p < 128; p++) acc = fmaf(w[p], e[p * 3], acc);
            g_W3Eg[((size_t)t * RR + rb + rr) * 192 + j * 3 + o] = acc;
        }
        if (tid < nr * 3) {
            int rr = tid / 3, o = tid - rr * 3;
            const float* b = gub3 + t * 128;
            const float* e = sE6 + rr * 384 + o;
            float a = 0.f;
#pragma unroll 8
            for (int p = 0; p < 128; p++) a = fmaf(b[p], e[p * 3], a);
            g_b3Eg[(t * RR + rb + rr) * 3 + o] = a;
        }
    } else {
        for (int idx = tid; idx < 8192; idx += 256) {
            int j = idx >> 7, p = idx & 127;
            sW[j * 129 + p] = uW3[idx];
        }
        for (int idx = tid; idx < nr * 128; idx += 256) sE6[idx] = uE[rb * 128 + idx];
        __syncthreads();
        for (int idx = tid; idx < nr * 64; idx += 256) {
            int rr = idx >> 6, j = idx & 63;
            const float* w = sW + j * 129;
            const float* e = sE6 + rr * 128;
            float acc = 0.f;
#pragma unroll 8
            for (int p = 0; p < 128; p++) acc = fmaf(w[p], e[p], acc);
            g_W3Eu[(rb + rr) * 64 + j] = acc;
        }
        if (tid < nr) {
            const float* e = sE6 + tid * 128;
            float acc = 0.f;
#pragma unroll 8
            for (int p = 0; p < 128; p++) acc = fmaf(ub3[p], e[p], acc);
            g_b3Eu[rb + tid] = acc;
        }
    }
}

// ---------------- C table build: FFMA2 + coalesced float4 stores ----------------
#define CPAD 68
#define SMEM_C_FLOATS (2 * 128 * CPAD)
__global__ void __launch_bounds__(256, 1)
k_build_C(const float* __restrict__ jxW3, const float* __restrict__ jxb3,
          const float* __restrict__ jump_r, const float* __restrict__ jump_l) {
    extern __shared__ float smc[];
    float* smA = smc;                 // [128][68]: smA[p][j]
    float* smB = smc + 128 * CPAD;    // [128][68]: smB[p][n]
    int nblk = blockIdx.x, t = blockIdx.y, tid = threadIdx.x;

    for (int idx = tid; idx < 8192; idx += 256) {
        int j = idx >> 7, p = idx & 127;
        smA[p * CPAD + j] = jxW3[(size_t)t * 8192 + idx];
    }
    for (int idx = tid; idx < 8192; idx += 256) {
        int n = idx >> 7, p = idx & 127;
        int n_g = nblk * 64 + n;
        float b = 0.f;
        if (n_g < RR * 81) {
            int r = n_g / 81, d = n_g - r * 81;
            float jl = 0.f;
            if (d > 40)      jl = jump_l[(d - 41) * PP + p];
            else if (d < 40) jl = jump_l[(79 - d) * PP + p];
            b = jump_r[r * PP + p] * (jl - g_mcjump[r * PP + p] * DT_F);
        }
        smB[p * CPAD + n] = b;
    }
    __syncthreads();

    int tx = tid & 15, ty = tid >> 4;
    ull acc[4][2];
#pragma unroll
    for (int n = 0; n < 4; n++) { acc[n][0] = 0ull; acc[n][1] = 0ull; }
#pragma unroll 4
    for (int p = 0; p < 128; p++) {
        longlong2 aj = *(const longlong2*)(smA + p * CPAD + tx * 4);
        float4 bn = *(const float4*)(smB + p * CPAD + ty * 4);
        ull b0 = pack2(bn.x, bn.x), b1 = pack2(bn.y, bn.y);
        ull b2 = pack2(bn.z, bn.z), b3 = pack2(bn.w, bn.w);
        acc[0][0] = fma2(b0, (ull)aj.x, acc[0][0]);
        acc[0][1] = fma2(b0, (ull)aj.y, acc[0][1]);
        acc[1][0] = fma2(b1, (ull)aj.x, acc[1][0]);
        acc[1][1] = fma2(b1, (ull)aj.y, acc[1][1]);
        acc[2][0] = fma2(b2, (ull)aj.x, acc[2][0]);
        acc[2][1] = fma2(b2, (ull)aj.y, acc[2][1]);
        acc[3][0] = fma2(b3, (ull)aj.x, acc[3][0]);
        acc[3][1] = fma2(b3, (ull)aj.y, acc[3][1]);
    }
#pragma unroll
    for (int n = 0; n < 4; n++) {
        int n_g = nblk * 64 + ty * 4 + n;
        float2 lo = unpk(acc[n][0]);
        float2 hi = unpk(acc[n][1]);
        float4 v; v.x = lo.x; v.y = lo.y; v.z = hi.x; v.w = hi.y;
        *(float4*)(g_C + ((size_t)t * NPAD + n_g) * CROW + tx * 4) = v;
    }
    if (tid < 64) {
        int n_g = nblk * 64 + tid;
        const float* b3 = jxb3 + t * 128;
        float c0 = 0.f;
#pragma unroll 4
        for (int p = 0; p < 128; p++) c0 = fmaf(b3[p], smB[p * CPAD + tid], c0);
        size_t base = ((size_t)t * NPAD + n_g) * CROW;
        g_C[base + 64] = c0;
        g_C[base + 65] = 0.f; g_C[base + 66] = 0.f; g_C[base + 67] = 0.f;
    }
}

// ---------------- geometry pass: trajectory only, NN-free ----------------
__global__ void __launch_bounds__(128)
k_geom(const int* __restrict__ rt0, const float* __restrict__ xt0,
       const float* __restrict__ dBt, const float* __restrict__ u_jump,
       const float* __restrict__ u_size, float* __restrict__ out) {
    __shared__ float sJM[RR * 80];
    __shared__ float sCR[RR];
    __shared__ float sCF[RR];
    int tid = threadIdx.x;
    for (int idx = tid; idx < RR * 80; idx += 128) sJM[idx] = g_jm[idx];
    for (int idx = tid; idx < RR; idx += 128) {
        sCR[idx] = g_cr[idx];
        sCF[idx] = g_cfr[idx];
    }
    __syncthreads();

    int i = blockIdx.x * 128 + tid;
    const float sqDT = 0.17677669529663688985f;   // sqrt(1/32)
    const float sq2D = 1.41421356237309504880f;   // sqrt(2)
    int rt = rt0[i];
    float x0 = xt0[i * 3 + 0], x1 = xt0[i * 3 + 1], x2 = xt0[i * 3 + 2];
    float xi0 = x0, xi1 = x1, xi2 = x2;
    float sgn = 1.f, fun = 0.f;

#pragma unroll 1
    for (int t = 0; t < NSTEP; t++) {
        int ridx = rt - RMIN;
        float uj = u_jump[t * BB + i];
        int drt = 0;
        if (uj < sCR[ridx] * DT_F) {
            int ind = ubound80(sJM + ridx * 80, u_size[t * BB + i]);
            drt = (ind < GAP) ? (ind + 1) : -(ind - GAP + 1);
        }

        float rn = sqrtf(x0 * x0 + x1 * x1 + x2 * x2);
        float cz = fminf(fmaxf(x2 / rn, -1.0f), 1.0f);
        float theta = acosf(cz) - 0.5f * PI_F;
        float phi = atan2f(x1, x0);
        float st, ct, sp, cpv;
        __sincosf(theta, &st, &ct);
        __sincosf(phi, &sp, &cpv);
        float T00 = cpv * ct, T01 = -sp,  T02 = cpv * st;
        float T10 = sp * ct,  T11 = cpv,  T12 = sp * st;
        float T20 = -st,      T22 = ct;

        float2 db = ((const float2*)dBt)[t * BB + i];
        float dB0 = db.x * sqDT, dB1 = db.y * sqDT;
        float rtf = (float)rt;
        float c1 = sq2D / rtf;
        float ef = __expf(-fun);

        float m0 = ef * c1 * (T01 * dB1 - T02 * dB0);
        float m1 = ef * c1 * (T11 * dB1 - T12 * dB0);
        float m2 = -ef * c1 * sgn * T22 * dB0;
        float4 av; av.x = xi0; av.y = xi1; av.z = xi2; av.w = ef;
        g_A[t * BB + i] = av;
        float4 mv; mv.x = m0; mv.y = m1; mv.z = m2;
        mv.w = __int_as_float(ridx | ((drt + 40) << 8));
        g_M[t * BB + i] = mv;

        fun += sCF[ridx] * DT_F;

        float dX20 = c1 * dB0, dX21 = c1 * dB1;
        float th_d = dX20 + 0.5f * PI_F;
        float sth, cth, sph, cph;
        __sincosf(th_d, &sth, &cth);
        __sincosf(dX21, &sph, &cph);
        float d30 = sth * cph - 1.0f;
        float d31 = sth * sph;
        float d32 = cth;
        float dX0 = T00 * d30 + T01 * d31 + T02 * d32;
        float dX1 = T10 * d30 + T11 * d31 + T12 * d32;
        float dX2 = T20 * d30 + T22 * d32;     // T21 = 0
        x0 += dX0; x1 += dX1; x2 += dX2;
        xi0 += dX0; xi1 += dX1; xi2 += sgn * dX2;
        rt += drt;
        if (xi2 < 0.f) { xi2 = -xi2; sgn = -sgn; }
    }

    float ef = __expf(-fun);
    out[BB + i] = (xi0 * xi0 + xi1 * xi1 + xi2 * xi2) / (float)rt * ef;
}

// ---------------- helpers ----------------
__device__ __forceinline__ void cp4s(float* dst, const float* __restrict__ src,
                                     int nfl, int tid) {
    const float4* s = (const float4*)src;
    float4* d = (float4*)dst;
    int n4 = nfl >> 2;
    for (int i = tid; i < n4; i += 256) d[i] = s[i];
}

// hardware tanh (MUFU.TANH, sm_75+)
__device__ __forceinline__ float tanh_fast(float x) {
    float y;
    asm("tanh.approx.f32 %0, %1;" : "=f"(y) : "f"(x));
    return y;
}

// layer1: x(3) -> tanh(64); weights W1 @0 [3][64], b1 @192
__device__ __forceinline__ void layer1(const float* __restrict__ W,
                                       float x0, float x1, float x2, float* h1) {
#pragma unroll
    for (int j = 0; j < 64; j += 4) {
        float4 wa = *(const float4*)(W + j);
        float4 wb = *(const float4*)(W + 64 + j);
        float4 wc = *(const float4*)(W + 128 + j);
        float4 bb = *(const float4*)(W + 192 + j);
        h1[j + 0] = tanh_fast(fmaf(x0, wa.x, fmaf(x1, wb.x, fmaf(x2, wc.x, bb.x))));
        h1[j + 1] = tanh_fast(fmaf(x0, wa.y, fmaf(x1, wb.y, fmaf(x2, wc.y, bb.y))));
        h1[j + 2] = tanh_fast(fmaf(x0, wa.z, fmaf(x1, wb.z, fmaf(x2, wc.z, bb.z))));
        h1[j + 3] = tanh_fast(fmaf(x0, wa.w, fmaf(x1, wb.w, fmaf(x2, wc.w, bb.w))));
    }
}

// layer2 16-output pass via packed FFMA2: y[16] = tanh(h1 @ W2[:, cbase:cbase+16] + b2)
__device__ __forceinline__ void layer2_pass16(const float* __restrict__ W2,
                                              const float* __restrict__ b2,
                                              const float* __restrict__ h1,
                                              int cbase, float* y) {
    ull A[8];
    {
        const longlong2* bb = (const longlong2*)(b2 + cbase);
#pragma unroll
        for (int q = 0; q < 4; q++) {
            longlong2 v = bb[q];
            A[2 * q] = (ull)v.x; A[2 * q + 1] = (ull)v.y;
        }
    }
#pragma unroll
    for (int j = 0; j < 64; j++) {
        ull hp = pack2(h1[j], h1[j]);
        const longlong2* w = (const longlong2*)(W2 + j * 64 + cbase);
#pragma unroll
        for (int q = 0; q < 4; q++) {
            longlong2 wv = w[q];
            A[2 * q]     = fma2(hp, (ull)wv.x, A[2 * q]);
            A[2 * q + 1] = fma2(hp, (ull)wv.y, A[2 * q + 1]);
        }
    }
#pragma unroll
    for (int q = 0; q < 8; q++) {
        float2 f = unpk(A[q]);
        y[2 * q]     = tanh_fast(f.x);
        y[2 * q + 1] = tanh_fast(f.y);
    }
}

// ---------------- NN kernel: grid (NCH chunks, t) ----------------
// smem: gW 4416 | jW 4416 | E 7872 | B3E 128  = 16832 floats
#define SN_GW   0
#define SN_JW   4416
#define SN_E    8832
#define SN_B3E  16704
#define SN_TOT  16832
__global__ void __launch_bounds__(256, 2)
k_nn(const float* __restrict__ xt0, const int* __restrict__ rt0,
     const float* __restrict__ uW1, const float* __restrict__ ub1,
     const float* __restrict__ uW2, const float* __restrict__ ub2,
     const float* __restrict__ guW1, const float* __restrict__ gub1,
     const float* __restrict__ guW2, const float* __restrict__ gub2,
     const float* __restrict__ jxW1, const float* __restrict__ jxb1,
     const float* __restrict__ jxW2, const float* __restrict__ jxb2) {
    extern __shared__ float sm[];
    int t = blockIdx.y, tid = threadIdx.x;

    if (t < NSTEP) {
        cp4s(sm + SN_GW,        guW1 + t * 192,  192,  tid);
        cp4s(sm + SN_GW + 192,  gub1 + t * 64,   64,   tid);
        cp4s(sm + SN_GW + 256,  guW2 + t * 4096, 4096, tid);
        cp4s(sm + SN_GW + 4352, gub2 + t * 64,   64,   tid);
        cp4s(sm + SN_JW,        jxW1 + t * 192,  192,  tid);
        cp4s(sm + SN_JW + 192,  jxb1 + t * 64,   64,   tid);
        cp4s(sm + SN_JW + 256,  jxW2 + t * 4096, 4096, tid);
        cp4s(sm + SN_JW + 4352, jxb2 + t * 64,   64,   tid);
        const float* wsrc = g_W3Eg + (size_t)t * RR * 192;
        for (int idx = tid; idx < RR * 192; idx += 256) {
            int r = idx / 192, c = idx - r * 192;
            sm[SN_E + c * 41 + r] = wsrc[idx];
        }
        const float* bsrc = g_b3Eg + t * RR * 3;
        for (int idx = tid; idx < RR * 3; idx += 256) {
            int r = idx / 3, o = idx - r * 3;
            sm[SN_B3E + o * 41 + r] = bsrc[idx];
        }
    } else {
        cp4s(sm + SN_GW, uW1, 192, tid);
        cp4s(sm + SN_GW + 192, ub1, 64, tid);
        cp4s(sm + SN_GW + 256, uW2, 4096, tid);
        cp4s(sm + SN_GW + 4352, ub2, 64, tid);
        for (int idx = tid; idx < RR * 64; idx += 256) {
            int r = idx >> 6, j = idx & 63;
            sm[SN_E + j * 41 + r] = g_W3Eu[idx];
        }
        for (int idx = tid; idx < RR; idx += 256) sm[SN_B3E + idx] = g_b3Eu[idx];
    }
    __syncthreads();

    float h1[64];
    float y[16];

    if (t < NSTEP) {
#pragma unroll 1
        for (int k = 0; k < 8; k++) {
            int i = blockIdx.x * 256 + k * (NCH * 256) + tid;
            if (i >= BB) break;
            float4 av = g_A[t * BB + i];
            float4 mv = g_M[t * BB + i];
            int bits = __float_as_int(mv.w);
            int ridx = bits & 0xFF;
            int n = ridx * 81 + (bits >> 8);
            const float* crow = g_C + ((size_t)t * NPAD + n) * CROW;
            asm volatile("prefetch.global.L1 [%0];" :: "l"(crow));
            asm volatile("prefetch.global.L1 [%0];" :: "l"(crow + 32));
            asm volatile("prefetch.global.L1 [%0];" :: "l"(crow + 64));

            // ---- g-net ----
            layer1(sm + SN_GW, av.x, av.y, av.z, h1);
            float gu0 = sm[SN_B3E + ridx];
            float gu1 = sm[SN_B3E + 41 + ridx];
            float gu2 = sm[SN_B3E + 82 + ridx];
#pragma unroll 1
            for (int pass = 0; pass < 4; pass++) {
                layer2_pass16(sm + SN_GW + 256, sm + SN_GW + 4352, h1, pass * 16, y);
#pragma unroll
                for (int q = 0; q < 16; q++) {
                    const float* e = sm + SN_E + ((pass * 16 + q) * 3) * 41 + ridx;
                    gu0 = fmaf(y[q], e[0], gu0);
                    gu1 = fmaf(y[q], e[41], gu1);
                    gu2 = fmaf(y[q], e[82], gu2);
                }
            }

            // ---- j-net ----
            layer1(sm + SN_JW, av.x, av.y, av.z, h1);
            float jmp = crow[64];   // c0
            const float4* crow4 = (const float4*)crow;
#pragma unroll 1
            for (int pass = 0; pass < 4; pass++) {
                layer2_pass16(sm + SN_JW + 256, sm + SN_JW + 4352, h1, pass * 16, y);
                float4 c0 = crow4[pass * 4 + 0];
                float4 c1 = crow4[pass * 4 + 1];
                float4 c2 = crow4[pass * 4 + 2];
                float4 c3 = crow4[pass * 4 + 3];
                jmp = fmaf(y[0],  c0.x, jmp); jmp = fmaf(y[1],  c0.y, jmp);
                jmp = fmaf(y[2],  c0.z, jmp); jmp = fmaf(y[3],  c0.w, jmp);
                jmp = fmaf(y[4],  c1.x, jmp); jmp = fmaf(y[5],  c1.y, jmp);
                jmp = fmaf(y[6],  c1.z, jmp); jmp = fmaf(y[7],  c1.w, jmp);
                jmp = fmaf(y[8],  c2.x, jmp); jmp = fmaf(y[9],  c2.y, jmp);
                jmp = fmaf(y[10], c2.z, jmp); jmp = fmaf(y[11], c2.w, jmp);
                jmp = fmaf(y[12], c3.x, jmp); jmp = fmaf(y[13], c3.y, jmp);
                jmp = fmaf(y[14], c3.z, jmp); jmp = fmaf(y[15], c3.w, jmp);
            }

            g_part[t * BB + i] = gu0 * mv.x + gu1 * mv.y + gu2 * mv.z + av.w * jmp;
        }
    } else {
        // u0 slice
#pragma unroll 1
        for (int k = 0; k < 8; k++) {
            int i = blockIdx.x * 256 + k * (NCH * 256) + tid;
            if (i >= BB) break;
            float x0 = xt0[i * 3 + 0], x1 = xt0[i * 3 + 1], x2 = xt0[i * 3 + 2];
            int ridx = rt0[i] - RMIN;
            layer1(sm + SN_GW, x0, x1, x2, h1);
            float u = sm[SN_B3E + ridx];
#pragma unroll 1
            for (int pass = 0; pass < 4; pass++) {
                layer2_pass16(sm + SN_GW + 256, sm + SN_GW + 4352, h1, pass * 16, y);
#pragma unroll
                for (int q = 0; q < 16; q++)
                    u = fmaf(y[q], sm[SN_E + (pass * 16 + q) * 41 + ridx], u);
            }
            g_part[NSTEP * BB + i] = u;
        }
    }
}

// ---------------- reduction ----------------
__global__ void __launch_bounds__(256)
k_reduce(float* __restrict__ out) {
    int i = blockIdx.x * 256 + threadIdx.x;
    float s = g_part[NSTEP * BB + i];
#pragma unroll 1
    for (int t = 0; t < NSTEP; t++) s += g_part[t * BB + i];
    out[i] = s;
}

// ---------------- launcher (multi-stream fork/join, capture-legal) ----------------
extern "C" void kernel_launch(void* const* d_in, const int* in_sizes, int n_in,
                              void* d_out, int out_size) {
    const int*   rt0    = (const int*)d_in[1];
    const float* xt0    = (const float*)d_in[2];
    const float* dBt    = (const float*)d_in[3];
    const float* u_jump = (const float*)d_in[4];
    const float* u_size = (const float*)d_in[5];
    const float* u_mc   = (const float*)d_in[6];
    const float* uW1 = (const float*)d_in[7];
    const float* ub1 = (const float*)d_in[8];
    const float* uW2 = (const float*)d_in[9];
    const float* ub2 = (const float*)d_in[10];
    const float* uW3 = (const float*)d_in[11];
    const float* ub3 = (const float*)d_in[12];
    const float* uE  = (const float*)d_in[13];
    const float* guW1 = (const float*)d_in[14];
    const float* gub1 = (const float*)d_in[15];
    const float* guW2 = (const float*)d_in[16];
    const float* gub2 = (const float*)d_in[17];
    const float* guW3 = (const float*)d_in[18];
    const float* gub3 = (const float*)d_in[19];
    const float* guE  = (const float*)d_in[20];
    const float* jxW1 = (const float*)d_in[21];
    const float* jxb1 = (const float*)d_in[22];
    const float* jxW2 = (const float*)d_in[23];
    const float* jxb2 = (const float*)d_in[24];
    const float* jxW3 = (const float*)d_in[25];
    const float* jxb3 = (const float*)d_in[26];
    const float* jump_r = (const float*)d_in[27];
    const float* jump_l = (const float*)d_in[28];
    float* out = (float*)d_out;

    // lazily-created side streams + events (host objects, no device memory)
    static cudaStream_t sA = 0, sB = 0;
    static cudaEvent_t evStart = 0, evTab = 0, evA = 0, evB = 0;
    if (sA == 0) {
        cudaStreamCreateWithFlags(&sA, cudaStreamNonBlocking);
        cudaStreamCreateWithFlags(&sB, cudaStreamNonBlocking);
        cudaEventCreateWithFlags(&evStart, cudaEventDisableTiming);
        cudaEventCreateWithFlags(&evTab, cudaEventDisableTiming);
        cudaEventCreateWithFlags(&evA, cudaEventDisableTiming);
        cudaEventCreateWithFlags(&evB, cudaEventDisableTiming);
    }

    cudaFuncSetAttribute(k_build_C, cudaFuncAttributeMaxDynamicSharedMemorySize,
                         SMEM_C_FLOATS * 4);
    cudaFuncSetAttribute(k_nn, cudaFuncAttributeMaxDynamicSharedMemorySize,
                         SN_TOT * 4);

    // fork sA at start: w3e depends only on kernel inputs
    cudaEventRecord(evStart, 0);
    cudaStreamWaitEvent(sA, evStart, 0);
    k_build_w3e<<<dim3((RR + RGRP - 1) / RGRP, NSTEP + 1), 256, 0, sA>>>(
        guW3, gub3, guE, uW3, ub3, uE);
    cudaEventRecord(evA, sA);

    // main stream: tables -> mc chain -> build_C
    k_tables<<<1, 64>>>();
    // fork sB after tables: geom needs g_jm/g_cr/g_cfr only
    cudaEventRecord(evTab, 0);
    cudaStreamWaitEvent(sB, evTab, 0);
    k_geom<<<BB / 128, 128, 0, sB>>>(rt0, xt0, dBt, u_jump, u_size, out);
    cudaEventRecord(evB, sB);

    k_mc_hist<<<MCH_BLOCKS, 256>>>(u_mc);
    k_mc_combine<<<(RR * PP + 127) / 128, 128>>>(jump_l);
    k_build_C<<<dim3(NBLK, NSTEP), 256, SMEM_C_FLOATS * 4>>>(jxW3, jxb3, jump_r, jump_l);

    // join: k_nn needs w3e outputs, geom outputs, and C table
    cudaStreamWaitEvent(0, evA, 0);
    cudaStreamWaitEvent(0, evB, 0);
    k_nn<<<dim3(NCH, NSTEP + 1), 256, SN_TOT * 4>>>(
        xt0, rt0, uW1, ub1, uW2, ub2,
        guW1, gub1, guW2, gub2,
        jxW1, jxb1, jxW2, jxb2);
    k_reduce<<<BB / 256, 256>>>(out);
    (void)in_sizes; (void)n_in; (void)out_size;
}

// round 17
// speedup vs baseline: 1.2341x; 1.0076x over previous
#include <cuda_runtime.h>
#include <math.h>

#define RMIN 10
#define GAP  40
#define RR   41
#define PP   128
#define NSTEP 32
#define BB   16384
#define MCN  10000
#define DT_F 0.03125f
#define PI_F 3.14159265358979323846f
#define NPAD 3328       // 41*81 = 3321 padded
#define NBLK 52
#define CROW 68         // 64 coeffs + c0 + 3 pad
#define NCH  9          // k_nn sample chunks (9*33 = 297 blocks ~ 1 wave)
#define RGRP 6
#define MCH_BLOCKS 128

typedef unsigned long long ull;

// ---------------- f32x2 packed helpers ----------------
__device__ __forceinline__ ull pack2(float lo, float hi) {
    ull r;
    asm("mov.b64 %0, {%1, %2};" : "=l"(r) : "f"(lo), "f"(hi));
    return r;
}
__device__ __forceinline__ ull fma2(ull a, ull b, ull c) {
    ull d;
    asm("fma.rn.f32x2 %0, %1, %2, %3;" : "=l"(d) : "l"(a), "l"(b), "l"(c));
    return d;
}
__device__ __forceinline__ float2 unpk(ull v) {
    float2 f;
    asm("mov.b64 {%0, %1}, %2;" : "=f"(f.x), "=f"(f.y) : "l"(v));
    return f;
}

// ---------------- device scratch ----------------
__device__ float g_jm[RR * 80];
__device__ float g_cr[RR];
__device__ float g_cfr[RR];
__device__ int   g_hist[RR * 80];
__device__ float g_mcjump[RR * PP];
__device__ float g_W3Eu[RR * 64];
__device__ float g_b3Eu[RR];
__device__ float g_W3Eg[NSTEP * RR * 192];
__device__ float g_b3Eg[NSTEP * RR * 3];
__device__ float g_C[(size_t)NSTEP * NPAD * CROW];   // ~29 MB
__device__ float4 g_A[NSTEP * BB];                   // xi0,xi1,xi2, ef
__device__ float4 g_M[NSTEP * BB];                   // m0,m1,m2, bits(ridx|d<<8)
__device__ float  g_part[(NSTEP + 1) * BB];

// upper bound on non-decreasing 80-row: #(row[j] <= u)
__device__ __forceinline__ int ubound80(const float* __restrict__ row, float u) {
    int lo = 0, hi = 80;
    while (lo < hi) {
        int mid = (lo + hi) >> 1;
        if (row[mid] <= u) lo = mid + 1; else hi = mid;
    }
    return lo;
}

// ---------------- tables (+ hist zero) ----------------
__global__ void k_tables() {
    int tid = threadIdx.x;
    for (int i = tid; i < RR * 80; i += 64) g_hist[i] = 0;
    int r = tid;
    if (r >= RR) return;
    float cum = 0.f, slam = 0.f, smu = 0.f;
    for (int k = 1; k <= GAP; k++) {
        float kk = (float)k;
        float lam = ((r + RMIN + k) <= RMIN + GAP) ? 1.0f / (kk * kk) : 0.0f;
        slam += lam; cum += lam;
        g_jm[r * 80 + (k - 1)] = cum;
    }
    for (int k = 1; k <= GAP; k++) {
        float kk = (float)k;
        float mu = ((r + RMIN - k) >= RMIN) ? 1.0f / (kk * kk) : 0.0f;
        smu += mu; cum += mu;
        g_jm[r * 80 + GAP + (k - 1)] = cum;
    }
    g_cr[r] = cum;
    g_cfr[r] = slam + smu - cum;
    for (int j = 0; j < 80; j++) g_jm[r * 80 + j] /= cum;
}

// MC hist: smem jm + smem histogram, 4-way ILP-batched binary searches
__global__ void __launch_bounds__(256)
k_mc_hist(const float* __restrict__ u_mc) {
    __shared__ float sJM[RR * 80];
    __shared__ int   sH[RR * 80];
    int tid = threadIdx.x;
    for (int idx = tid; idx < RR * 80; idx += 256) {
        sJM[idx] = g_jm[idx];
        sH[idx] = 0;
    }
    __syncthreads();

    const int STRIDE = MCH_BLOCKS * 256;
    int gid = blockIdx.x * 256 + tid;
#pragma unroll 1
    for (int i = gid; i < MCN * RR; i += 4 * STRIDE) {
        int  id[4]; float u[4]; int lo[4], hi[4]; bool vld[4];
#pragma unroll
        for (int q = 0; q < 4; q++) {
            id[q] = i + q * STRIDE;
            vld[q] = id[q] < MCN * RR;
            u[q] = vld[q] ? u_mc[id[q]] : 2.0f;
            int r = vld[q] ? (id[q] % RR) : 0;
            lo[q] = r * 80;
            hi[q] = r * 80 + 80;
        }
        // 7 fixed branchless steps (2^7 >= 81) — 4 independent LDS chains
#pragma unroll
        for (int s = 0; s < 7; s++) {
#pragma unroll
            for (int q = 0; q < 4; q++) {
                if (lo[q] < hi[q]) {
                    int mid = (lo[q] + hi[q]) >> 1;
                    bool c = sJM[mid] <= u[q];
                    lo[q] = c ? mid + 1 : lo[q];
                    hi[q] = c ? hi[q] : mid;
                }
            }
        }
#pragma unroll
        for (int q = 0; q < 4; q++)
            if (vld[q]) atomicAdd(&sH[lo[q]], 1);
    }
    __syncthreads();
    for (int idx = tid; idx < RR * 80; idx += 256) {
        int v = sH[idx];
        if (v) atomicAdd(&g_hist[idx], v);
    }
}

__global__ void k_mc_combine(const float* __restrict__ jump_l) {
    int idx = blockIdx.x * blockDim.x + threadIdx.x;
    if (idx >= RR * PP) return;
    int r = idx / PP, p = idx % PP;
    float s = 0.f;
    for (int b = 0; b < 80; b++) {
        int c = g_hist[r * 80 + b];
        if (c) s += (float)c * jump_l[b * PP + p];
    }
    g_mcjump[idx] = s * (1.0f / (float)MCN) * g_cr[r];
}

// ---------------- W3E build: one CTA per (r-group of 6, t); t=NSTEP -> u-net ----------------
__global__ void __launch_bounds__(256, 1)
k_build_w3e(const float* __restrict__ guW3, const float* __restrict__ gub3,
            const float* __restrict__ guE,
            const float* __restrict__ uW3, const float* __restrict__ ub3,
            const float* __restrict__ uE) {
    __shared__ float sW[64 * 129];
    __shared__ float sE6[RGRP * 384];
    int rb = blockIdx.x * RGRP, t = blockIdx.y, tid = threadIdx.x;
    int nr = (RR - rb < RGRP) ? (RR - rb) : RGRP;
    if (t < NSTEP) {
        for (int idx = tid; idx < 8192; idx += 256) {
            int j = idx >> 7, p = idx & 127;
            sW[j * 129 + p] = guW3[(size_t)t * 8192 + idx];
        }
        for (int idx = tid; idx < nr * 384; idx += 256)
            sE6[idx] = guE[((size_t)t * RR + rb) * 384 + idx];
        __syncthreads();
        for (int idx = tid; idx < nr * 192; idx += 256) {
            int rr = idx / 192, c = idx - rr * 192;
            int j = c & 63, o = c >> 6;
            const float* w = sW + j * 129;
            const float* e = sE6 + rr * 384 + o;
            float acc = 0.f;
#pragma unroll 8
            for (int p = 0; p < 128; p++) acc = fmaf(w[p], e[p * 3], acc);
            g_W3Eg[((size_t)t * RR + rb + rr) * 192 + j * 3 + o] = acc;
        }
        if (tid < nr * 3) {
            int rr = tid / 3, o = tid - rr * 3;
            const float* b = gub3 + t * 128;
            const float* e = sE6 + rr * 384 + o;
            float a = 0.f;
#pragma unroll 8
            for (int p = 0; p < 128; p++) a = fmaf(b[p], e[p * 3], a);
            g_b3Eg[(t * RR + rb + rr) * 3 + o] = a;
        }
    } else {
        for (int idx = tid; idx < 8192; idx += 256) {
            int j = idx >> 7, p = idx & 127;
            sW[j * 129 + p] = uW3[idx];
        }
        for (int idx = tid; idx < nr * 128; idx += 256) sE6[idx] = uE[rb * 128 + idx];
        __syncthreads();
        for (int idx = tid; idx < nr * 64; idx += 256) {
            int rr = idx >> 6, j = idx & 63;
            const float* w = sW + j * 129;
            const float* e = sE6 + rr * 128;
            float acc = 0.f;
#pragma unroll 8
            for (int p = 0; p < 128; p++) acc = fmaf(w[p], e[p], acc);
            g_W3Eu[(rb + rr) * 64 + j] = acc;
        }
        if (tid < nr) {
            const float* e = sE6 + tid * 128;
            float acc = 0.f;
#pragma unroll 8
            for (int p = 0; p < 128; p++) acc = fmaf(ub3[p], e[p], acc);
            g_b3Eu[rb + tid] = acc;
        }
    }
}

// ---------------- C table build: FFMA2 + coalesced float4 stores ----------------
#define CPAD 68
#define SMEM_C_FLOATS (2 * 128 * CPAD)
__global__ void __launch_bounds__(256, 1)
k_build_C(const float* __restrict__ jxW3, const float* __restrict__ jxb3,
          const float* __restrict__ jump_r, const float* __restrict__ jump_l) {
    extern __shared__ float smc[];
    float* smA = smc;                 // [128][68]: smA[p][j]
    float* smB = smc + 128 * CPAD;    // [128][68]: smB[p][n]
    int nblk = blockIdx.x, t = blockIdx.y, tid = threadIdx.x;

    for (int idx = tid; idx < 8192; idx += 256) {
        int j = idx >> 7, p = idx & 127;
        smA[p * CPAD + j] = jxW3[(size_t)t * 8192 + idx];
    }
    for (int idx = tid; idx < 8192; idx += 256) {
        int n = idx >> 7, p = idx & 127;
        int n_g = nblk * 64 + n;
        float b = 0.f;
        if (n_g < RR * 81) {
            int r = n_g / 81, d = n_g - r * 81;
            float jl = 0.f;
            if (d > 40)      jl = jump_l[(d - 41) * PP + p];
            else if (d < 40) jl = jump_l[(79 - d) * PP + p];
            b = jump_r[r * PP + p] * (jl - g_mcjump[r * PP + p] * DT_F);
        }
        smB[p * CPAD + n] = b;
    }
    __syncthreads();

    int tx = tid & 15, ty = tid >> 4;
    ull acc[4][2];
#pragma unroll
    for (int n = 0; n < 4; n++) { acc[n][0] = 0ull; acc[n][1] = 0ull; }
#pragma unroll 4
    for (int p = 0; p < 128; p++) {
        longlong2 aj = *(const longlong2*)(smA + p * CPAD + tx * 4);
        float4 bn = *(const float4*)(smB + p * CPAD + ty * 4);
        ull b0 = pack2(bn.x, bn.x), b1 = pack2(bn.y, bn.y);
        ull b2 = pack2(bn.z, bn.z), b3 = pack2(bn.w, bn.w);
        acc[0][0] = fma2(b0, (ull)aj.x, acc[0][0]);
        acc[0][1] = fma2(b0, (ull)aj.y, acc[0][1]);
        acc[1][0] = fma2(b1, (ull)aj.x, acc[1][0]);
        acc[1][1] = fma2(b1, (ull)aj.y, acc[1][1]);
        acc[2][0] = fma2(b2, (ull)aj.x, acc[2][0]);
        acc[2][1] = fma2(b2, (ull)aj.y, acc[2][1]);
        acc[3][0] = fma2(b3, (ull)aj.x, acc[3][0]);
        acc[3][1] = fma2(b3, (ull)aj.y, acc[3][1]);
    }
#pragma unroll
    for (int n = 0; n < 4; n++) {
        int n_g = nblk * 64 + ty * 4 + n;
        float2 lo = unpk(acc[n][0]);
        float2 hi = unpk(acc[n][1]);
        float4 v; v.x = lo.x; v.y = lo.y; v.z = hi.x; v.w = hi.y;
        *(float4*)(g_C + ((size_t)t * NPAD + n_g) * CROW + tx * 4) = v;
    }
    if (tid < 64) {
        int n_g = nblk * 64 + tid;
        const float* b3 = jxb3 + t * 128;
        float c0 = 0.f;
#pragma unroll 4
        for (int p = 0; p < 128; p++) c0 = fmaf(b3[p], smB[p * CPAD + tid], c0);
        size_t base = ((size_t)t * NPAD + n_g) * CROW;
        g_C[base + 64] = c0;
        g_C[base + 65] = 0.f; g_C[base + 66] = 0.f; g_C[base + 67] = 0.f;
    }
}

// ---------------- geometry pass: trajectory only, NN-free ----------------
__global__ void __launch_bounds__(128)
k_geom(const int* __restrict__ rt0, const float* __restrict__ xt0,
       const float* __restrict__ dBt, const float* __restrict__ u_jump,
       const float* __restrict__ u_size, float* __restrict__ out) {
    __shared__ float sJM[RR * 80];
    __shared__ float sCR[RR];
    __shared__ float sCF[RR];
    int tid = threadIdx.x;
    for (int idx = tid; idx < RR * 80; idx += 128) sJM[idx] = g_jm[idx];
    for (int idx = tid; idx < RR; idx += 128) {
        sCR[idx] = g_cr[idx];
        sCF[idx] = g_cfr[idx];
    }
    __syncthreads();

    int i = blockIdx.x * 128 + tid;
    const float sqDT = 0.17677669529663688985f;   // sqrt(1/32)
    const float sq2D = 1.41421356237309504880f;   // sqrt(2)
    int rt = rt0[i];
    float x0 = xt0[i * 3 + 0], x1 = xt0[i * 3 + 1], x2 = xt0[i * 3 + 2];
    float xi0 = x0, xi1 = x1, xi2 = x2;
    float sgn = 1.f, fun = 0.f;

#pragma unroll 1
    for (int t = 0; t < NSTEP; t++) {
        int ridx = rt - RMIN;
        float uj = u_jump[t * BB + i];
        int drt = 0;
        if (uj < sCR[ridx] * DT_F) {
            int ind = ubound80(sJM + ridx * 80, u_size[t * BB + i]);
            drt = (ind < GAP) ? (ind + 1) : -(ind - GAP + 1);
        }

        float rn = sqrtf(x0 * x0 + x1 * x1 + x2 * x2);
        float cz = fminf(fmaxf(x2 / rn, -1.0f), 1.0f);
        float theta = acosf(cz) - 0.5f * PI_F;
        float phi = atan2f(x1, x0);
        float st, ct, sp, cpv;
        __sincosf(theta, &st, &ct);
        __sincosf(phi, &sp, &cpv);
        float T00 = cpv * ct, T01 = -sp,  T02 = cpv * st;
        float T10 = sp * ct,  T11 = cpv,  T12 = sp * st;
        float T20 = -st,      T22 = ct;

        float2 db = ((const float2*)dBt)[t * BB + i];
        float dB0 = db.x * sqDT, dB1 = db.y * sqDT;
        float rtf = (float)rt;
        float c1 = sq2D / rtf;
        float ef = __expf(-fun);

        float m0 = ef * c1 * (T01 * dB1 - T02 * dB0);
        float m1 = ef * c1 * (T11 * dB1 - T12 * dB0);
        float m2 = -ef * c1 * sgn * T22 * dB0;
        float4 av; av.x = xi0; av.y = xi1; av.z = xi2; av.w = ef;
        g_A[t * BB + i] = av;
        float4 mv; mv.x = m0; mv.y = m1; mv.z = m2;
        mv.w = __int_as_float(ridx | ((drt + 40) << 8));
        g_M[t * BB + i] = mv;

        fun += sCF[ridx] * DT_F;

        float dX20 = c1 * dB0, dX21 = c1 * dB1;
        float th_d = dX20 + 0.5f * PI_F;
        float sth, cth, sph, cph;
        __sincosf(th_d, &sth, &cth);
        __sincosf(dX21, &sph, &cph);
        float d30 = sth * cph - 1.0f;
        float d31 = sth * sph;
        float d32 = cth;
        float dX0 = T00 * d30 + T01 * d31 + T02 * d32;
        float dX1 = T10 * d30 + T11 * d31 + T12 * d32;
        float dX2 = T20 * d30 + T22 * d32;     // T21 = 0
        x0 += dX0; x1 += dX1; x2 += dX2;
        xi0 += dX0; xi1 += dX1; xi2 += sgn * dX2;
        rt += drt;
        if (xi2 < 0.f) { xi2 = -xi2; sgn = -sgn; }
    }

    float ef = __expf(-fun);
    out[BB + i] = (xi0 * xi0 + xi1 * xi1 + xi2 * xi2) / (float)rt * ef;
}

// ---------------- helpers ----------------
__device__ __forceinline__ void cp4s(float* dst, const float* __restrict__ src,
                                     int nfl, int tid) {
    const float4* s = (const float4*)src;
    float4* d = (float4*)dst;
    int n4 = nfl >> 2;
    for (int i = tid; i < n4; i += 256) d[i] = s[i];
}

// hardware tanh (MUFU.TANH, sm_75+)
__device__ __forceinline__ float tanh_fast(float x) {
    float y;
    asm("tanh.approx.f32 %0, %1;" : "=f"(y) : "f"(x));
    return y;
}

// layer1: x(3) -> tanh(64); weights W1 @0 [3][64], b1 @192
__device__ __forceinline__ void layer1(const float* __restrict__ W,
                                       float x0, float x1, float x2, float* h1) {
#pragma unroll
    for (int j = 0; j < 64; j += 4) {
        float4 wa = *(const float4*)(W + j);
        float4 wb = *(const float4*)(W + 64 + j);
        float4 wc = *(const float4*)(W + 128 + j);
        float4 bb = *(const float4*)(W + 192 + j);
        h1[j + 0] = tanh_fast(fmaf(x0, wa.x, fmaf(x1, wb.x, fmaf(x2, wc.x, bb.x))));
        h1[j + 1] = tanh_fast(fmaf(x0, wa.y, fmaf(x1, wb.y, fmaf(x2, wc.y, bb.y))));
        h1[j + 2] = tanh_fast(fmaf(x0, wa.z, fmaf(x1, wb.z, fmaf(x2, wc.z, bb.z))));
        h1[j + 3] = tanh_fast(fmaf(x0, wa.w, fmaf(x1, wb.w, fmaf(x2, wc.w, bb.w))));
    }
}

// layer2 16-output pass via packed FFMA2: y[16] = tanh(h1 @ W2[:, cbase:cbase+16] + b2)
__device__ __forceinline__ void layer2_pass16(const float* __restrict__ W2,
                                              const float* __restrict__ b2,
                                              const float* __restrict__ h1,
                                              int cbase, float* y) {
    ull A[8];
    {
        const longlong2* bb = (const longlong2*)(b2 + cbase);
#pragma unroll
        for (int q = 0; q < 4; q++) {
            longlong2 v = bb[q];
            A[2 * q] = (ull)v.x; A[2 * q + 1] = (ull)v.y;
        }
    }
#pragma unroll
    for (int j = 0; j < 64; j++) {
        ull hp = pack2(h1[j], h1[j]);
        const longlong2* w = (const longlong2*)(W2 + j * 64 + cbase);
#pragma unroll
        for (int q = 0; q < 4; q++) {
            longlong2 wv = w[q];
            A[2 * q]     = fma2(hp, (ull)wv.x, A[2 * q]);
            A[2 * q + 1] = fma2(hp, (ull)wv.y, A[2 * q + 1]);
        }
    }
#pragma unroll
    for (int q = 0; q < 8; q++) {
        float2 f = unpk(A[q]);
        y[2 * q]     = tanh_fast(f.x);
        y[2 * q + 1] = tanh_fast(f.y);
    }
}

// ---------------- NN kernel: grid (NCH chunks, t) ----------------
// smem: gW 4416 | jW 4416 | E 7872 | B3E 128  = 16832 floats
#define SN_GW   0
#define SN_JW   4416
#define SN_E    8832
#define SN_B3E  16704
#define SN_TOT  16832
__global__ void __launch_bounds__(256, 2)
k_nn(const float* __restrict__ xt0, const int* __restrict__ rt0,
     const float* __restrict__ uW1, const float* __restrict__ ub1,
     const float* __restrict__ uW2, const float* __restrict__ ub2,
     const float* __restrict__ guW1, const float* __restrict__ gub1,
     const float* __restrict__ guW2, const float* __restrict__ gub2,
     const float* __restrict__ jxW1, const float* __restrict__ jxb1,
     const float* __restrict__ jxW2, const float* __restrict__ jxb2) {
    extern __shared__ float sm[];
    int t = blockIdx.y, tid = threadIdx.x;

    if (t < NSTEP) {
        cp4s(sm + SN_GW,        guW1 + t * 192,  192,  tid);
        cp4s(sm + SN_GW + 192,  gub1 + t * 64,   64,   tid);
        cp4s(sm + SN_GW + 256,  guW2 + t * 4096, 4096, tid);
        cp4s(sm + SN_GW + 4352, gub2 + t * 64,   64,   tid);
        cp4s(sm + SN_JW,        jxW1 + t * 192,  192,  tid);
        cp4s(sm + SN_JW + 192,  jxb1 + t * 64,   64,   tid);
        cp4s(sm + SN_JW + 256,  jxW2 + t * 4096, 4096, tid);
        cp4s(sm + SN_JW + 4352, jxb2 + t * 64,   64,   tid);
        const float* wsrc = g_W3Eg + (size_t)t * RR * 192;
        for (int idx = tid; idx < RR * 192; idx += 256) {
            int r = idx / 192, c = idx - r * 192;
            sm[SN_E + c * 41 + r] = wsrc[idx];
        }
        const float* bsrc = g_b3Eg + t * RR * 3;
        for (int idx = tid; idx < RR * 3; idx += 256) {
            int r = idx / 3, o = idx - r * 3;
            sm[SN_B3E + o * 41 + r] = bsrc[idx];
        }
    } else {
        cp4s(sm + SN_GW, uW1, 192, tid);
        cp4s(sm + SN_GW + 192, ub1, 64, tid);
        cp4s(sm + SN_GW + 256, uW2, 4096, tid);
        cp4s(sm + SN_GW + 4352, ub2, 64, tid);
        for (int idx = tid; idx < RR * 64; idx += 256) {
            int r = idx >> 6, j = idx & 63;
            sm[SN_E + j * 41 + r] = g_W3Eu[idx];
        }
        for (int idx = tid; idx < RR; idx += 256) sm[SN_B3E + idx] = g_b3Eu[idx];
    }
    __syncthreads();

    float h1[64];
    float y[16];

    if (t < NSTEP) {
#pragma unroll 1
        for (int k = 0; k < 8; k++) {
            int i = blockIdx.x * 256 + k * (NCH * 256) + tid;
            if (i >= BB) break;
            float4 av = g_A[t * BB + i];
            float4 mv = g_M[t * BB + i];
            int bits = __float_as_int(mv.w);
            int ridx = bits & 0xFF;
            int n = ridx * 81 + (bits >> 8);
            const float* crow = g_C + ((size_t)t * NPAD + n) * CROW;
            asm volatile("prefetch.global.L1 [%0];" :: "l"(crow));
            asm volatile("prefetch.global.L1 [%0];" :: "l"(crow + 32));
            asm volatile("prefetch.global.L1 [%0];" :: "l"(crow + 64));

            // ---- g-net ----
            layer1(sm + SN_GW, av.x, av.y, av.z, h1);
            float gu0 = sm[SN_B3E + ridx];
            float gu1 = sm[SN_B3E + 41 + ridx];
            float gu2 = sm[SN_B3E + 82 + ridx];
#pragma unroll 1
            for (int pass = 0; pass < 4; pass++) {
                layer2_pass16(sm + SN_GW + 256, sm + SN_GW + 4352, h1, pass * 16, y);
#pragma unroll
                for (int q = 0; q < 16; q++) {
                    const float* e = sm + SN_E + ((pass * 16 + q) * 3) * 41 + ridx;
                    gu0 = fmaf(y[q], e[0], gu0);
                    gu1 = fmaf(y[q], e[41], gu1);
                    gu2 = fmaf(y[q], e[82], gu2);
                }
            }

            // ---- j-net ----
            layer1(sm + SN_JW, av.x, av.y, av.z, h1);
            float jmp = crow[64];   // c0
            const float4* crow4 = (const float4*)crow;
#pragma unroll 1
            for (int pass = 0; pass < 4; pass++) {
                layer2_pass16(sm + SN_JW + 256, sm + SN_JW + 4352, h1, pass * 16, y);
                float4 c0 = crow4[pass * 4 + 0];
                float4 c1 = crow4[pass * 4 + 1];
                float4 c2 = crow4[pass * 4 + 2];
                float4 c3 = crow4[pass * 4 + 3];
                jmp = fmaf(y[0],  c0.x, jmp); jmp = fmaf(y[1],  c0.y, jmp);
                jmp = fmaf(y[2],  c0.z, jmp); jmp = fmaf(y[3],  c0.w, jmp);
                jmp = fmaf(y[4],  c1.x, jmp); jmp = fmaf(y[5],  c1.y, jmp);
                jmp = fmaf(y[6],  c1.z, jmp); jmp = fmaf(y[7],  c1.w, jmp);
                jmp = fmaf(y[8],  c2.x, jmp); jmp = fmaf(y[9],  c2.y, jmp);
                jmp = fmaf(y[10], c2.z, jmp); jmp = fmaf(y[11], c2.w, jmp);
                jmp = fmaf(y[12], c3.x, jmp); jmp = fmaf(y[13], c3.y, jmp);
                jmp = fmaf(y[14], c3.z, jmp); jmp = fmaf(y[15], c3.w, jmp);
            }

            g_part[t * BB + i] = gu0 * mv.x + gu1 * mv.y + gu2 * mv.z + av.w * jmp;
        }
    } else {
        // u0 slice
#pragma unroll 1
        for (int k = 0; k < 8; k++) {
            int i = blockIdx.x * 256 + k * (NCH * 256) + tid;
            if (i >= BB) break;
            float x0 = xt0[i * 3 + 0], x1 = xt0[i * 3 + 1], x2 = xt0[i * 3 + 2];
            int ridx = rt0[i] - RMIN;
            layer1(sm + SN_GW, x0, x1, x2, h1);
            float u = sm[SN_B3E + ridx];
#pragma unroll 1
            for (int pass = 0; pass < 4; pass++) {
                layer2_pass16(sm + SN_GW + 256, sm + SN_GW + 4352, h1, pass * 16, y);
#pragma unroll
                for (int q = 0; q < 16; q++)
                    u = fmaf(y[q], sm[SN_E + (pass * 16 + q) * 41 + ridx], u);
            }
            g_part[NSTEP * BB + i] = u;
        }
    }
}

// ---------------- reduction ----------------
__global__ void __launch_bounds__(256)
k_reduce(float* __restrict__ out) {
    int i = blockIdx.x * 256 + threadIdx.x;
    float s = g_part[NSTEP * BB + i];
#pragma unroll 1
    for (int t = 0; t < NSTEP; t++) s += g_part[t * BB + i];
    out[i] = s;
}

// ---------------- launcher (multi-stream fork/join, capture-legal) ----------------
extern "C" void kernel_launch(void* const* d_in, const int* in_sizes, int n_in,
                              void* d_out, int out_size) {
    const int*   rt0    = (const int*)d_in[1];
    const float* xt0    = (const float*)d_in[2];
    const float* dBt    = (const float*)d_in[3];
    const float* u_jump = (const float*)d_in[4];
    const float* u_size = (const float*)d_in[5];
    const float* u_mc   = (const float*)d_in[6];
    const float* uW1 = (const float*)d_in[7];
    const float* ub1 = (const float*)d_in[8];
    const float* uW2 = (const float*)d_in[9];
    const float* ub2 = (const float*)d_in[10];
    const float* uW3 = (const float*)d_in[11];
    const float* ub3 = (const float*)d_in[12];
    const float* uE  = (const float*)d_in[13];
    const float* guW1 = (const float*)d_in[14];
    const float* gub1 = (const float*)d_in[15];
    const float* guW2 = (const float*)d_in[16];
    const float* gub2 = (const float*)d_in[17];
    const float* guW3 = (const float*)d_in[18];
    const float* gub3 = (const float*)d_in[19];
    const float* guE  = (const float*)d_in[20];
    const float* jxW1 = (const float*)d_in[21];
    const float* jxb1 = (const float*)d_in[22];
    const float* jxW2 = (const float*)d_in[23];
    const float* jxb2 = (const float*)d_in[24];
    const float* jxW3 = (const float*)d_in[25];
    const float* jxb3 = (const float*)d_in[26];
    const float* jump_r = (const float*)d_in[27];
    const float* jump_l = (const float*)d_in[28];
    float* out = (float*)d_out;

    // lazily-created side streams + events (host objects, no device memory)
    static cudaStream_t sA = 0, sB = 0;
    static cudaEvent_t evStart = 0, evTab = 0, evA = 0, evB = 0;
    if (sA == 0) {
        cudaStreamCreateWithFlags(&sA, cudaStreamNonBlocking);
        cudaStreamCreateWithFlags(&sB, cudaStreamNonBlocking);
        cudaEventCreateWithFlags(&evStart, cudaEventDisableTiming);
        cudaEventCreateWithFlags(&evTab, cudaEventDisableTiming);
        cudaEventCreateWithFlags(&evA, cudaEventDisableTiming);
        cudaEventCreateWithFlags(&evB, cudaEventDisableTiming);
    }

    cudaFuncSetAttribute(k_build_C, cudaFuncAttributeMaxDynamicSharedMemorySize,
                         SMEM_C_FLOATS * 4);
    cudaFuncSetAttribute(k_nn, cudaFuncAttributeMaxDynamicSharedMemorySize,
                         SN_TOT * 4);

    // fork sA at start: w3e depends only on kernel inputs
    cudaEventRecord(evStart, 0);
    cudaStreamWaitEvent(sA, evStart, 0);
    k_build_w3e<<<dim3((RR + RGRP - 1) / RGRP, NSTEP + 1), 256, 0, sA>>>(
        guW3, gub3, guE, uW3, ub3, uE);
    cudaEventRecord(evA, sA);

    // main stream: tables -> mc chain -> build_C
    k_tables<<<1, 64>>>();
    // fork sB after tables: geom needs g_jm/g_cr/g_cfr only
    cudaEventRecord(evTab, 0);
    cudaStreamWaitEvent(sB, evTab, 0);
    k_geom<<<BB / 128, 128, 0, sB>>>(rt0, xt0, dBt, u_jump, u_size, out);
    cudaEventRecord(evB, sB);

    k_mc_hist<<<MCH_BLOCKS, 256>>>(u_mc);
    k_mc_combine<<<(RR * PP + 127) / 128, 128>>>(jump_l);
    k_build_C<<<dim3(NBLK, NSTEP), 256, SMEM_C_FLOATS * 4>>>(jxW3, jxb3, jump_r, jump_l);

    // join: k_nn needs w3e outputs, geom outputs, and C table
    cudaStreamWaitEvent(0, evA, 0);
    cudaStreamWaitEvent(0, evB, 0);
    k_nn<<<dim3(NCH, NSTEP + 1), 256, SN_TOT * 4>>>(
        xt0, rt0, uW1, ub1, uW2, ub2,
        guW1, gub1, guW2, gub2,
        jxW1, jxb1, jxW2, jxb2);
    k_reduce<<<BB / 256, 256>>>(out);
    (void)in_sizes; (void)n_in; (void)out_size;
}